// round 1
// baseline (speedup 1.0000x reference)
#include <cuda_runtime.h>

#define DIN   512
#define NQKV  192
#define DH    64
#define SEQ   4096
#define NB    4
#define MTOT  (NB * SEQ)
#define DOUT  512

// Scratch (allocation-free rule: device globals)
__device__ float g_qkv[MTOT * NQKV];   // [row][192]: q|k|v
__device__ float g_attn[MTOT * DH];    // attention output [row][64]

// ---------------------------------------------------------------------------
// Kernel A: qkv = x @ W_qkv    (M=16384, K=512, N=192)
// 64x64 block tile, 256 threads, 4x4 micro-tile (rows 2ty+{0,1,32,33})
// ---------------------------------------------------------------------------
__global__ __launch_bounds__(256) void qkv_gemm_kernel(
    const float* __restrict__ x, const float* __restrict__ w)
{
    __shared__ float As[16 * 66];  // [k][m] transposed, pad 66
    __shared__ float Bs[16 * 68];  // [k][n], pad 68 (float4-aligned)

    const int t  = threadIdx.x;
    const int tx = t & 15, ty = t >> 4;
    const int m0 = blockIdx.x * 64;
    const int n0 = blockIdx.y * 64;

    const int lr = t >> 2, lk4 = t & 3;    // A-tile loader: row, k-quad
    const int bk = t >> 4, bn4 = t & 15;   // B-tile loader

    float acc[4][4] = {};

    for (int kt = 0; kt < DIN; kt += 16) {
        float4 av = *(const float4*)&x[(m0 + lr) * DIN + kt + lk4 * 4];
        float4 bv = *(const float4*)&w[(kt + bk) * NQKV + n0 + bn4 * 4];
        __syncthreads();
        As[(lk4 * 4 + 0) * 66 + lr] = av.x;
        As[(lk4 * 4 + 1) * 66 + lr] = av.y;
        As[(lk4 * 4 + 2) * 66 + lr] = av.z;
        As[(lk4 * 4 + 3) * 66 + lr] = av.w;
        *(float4*)&Bs[bk * 68 + bn4 * 4] = bv;
        __syncthreads();

        #pragma unroll
        for (int kk = 0; kk < 16; kk++) {
            float2 a0 = *(const float2*)&As[kk * 66 + 2 * ty];
            float2 a1 = *(const float2*)&As[kk * 66 + 2 * ty + 32];
            float2 b0 = *(const float2*)&Bs[kk * 68 + 2 * tx];
            float2 b1 = *(const float2*)&Bs[kk * 68 + 2 * tx + 32];
            float a[4] = {a0.x, a0.y, a1.x, a1.y};
            float b[4] = {b0.x, b0.y, b1.x, b1.y};
            #pragma unroll
            for (int i = 0; i < 4; i++)
                #pragma unroll
                for (int j = 0; j < 4; j++)
                    acc[i][j] += a[i] * b[j];
        }
    }

    #pragma unroll
    for (int i = 0; i < 4; i++) {
        int r = m0 + 2 * ty + (i & 1) + 32 * (i >> 1);
        *(float2*)&g_qkv[r * NQKV + n0 + 2 * tx]      = make_float2(acc[i][0], acc[i][1]);
        *(float2*)&g_qkv[r * NQKV + n0 + 2 * tx + 32] = make_float2(acc[i][2], acc[i][3]);
    }
}

// ---------------------------------------------------------------------------
// Kernel B: causal flash attention, Br=Bc=64, D=64. One block per (rowblk, b).
// ---------------------------------------------------------------------------
__device__ __forceinline__ float redmax16(float v) {
    v = fmaxf(v, __shfl_xor_sync(0xffffffffu, v, 1));
    v = fmaxf(v, __shfl_xor_sync(0xffffffffu, v, 2));
    v = fmaxf(v, __shfl_xor_sync(0xffffffffu, v, 4));
    v = fmaxf(v, __shfl_xor_sync(0xffffffffu, v, 8));
    return v;
}
__device__ __forceinline__ float redsum16(float v) {
    v += __shfl_xor_sync(0xffffffffu, v, 1);
    v += __shfl_xor_sync(0xffffffffu, v, 2);
    v += __shfl_xor_sync(0xffffffffu, v, 4);
    v += __shfl_xor_sync(0xffffffffu, v, 8);
    return v;
}

#define ATTN_SMEM_FLOATS (64 * 66 + 64 * 66 + 64 * 68)

__global__ __launch_bounds__(256) void attn_kernel()
{
    extern __shared__ float sm[];
    float* QsT = sm;                 // [d][r], pad 66
    float* KsT = sm + 64 * 66;       // [d][c], pad 66; reused as PsT [c][r]
    float* Vs  = sm + 2 * 64 * 66;   // [c][dv], pad 68

    const int b  = blockIdx.y;
    const int ib = gridDim.x - 1 - blockIdx.x;   // longest blocks first
    const int i0 = ib * 64;
    const int t  = threadIdx.x;
    const int tx = t & 15, ty = t >> 4;
    const float scale = 0.125f;   // 64^-0.5

    // Load Q tile transposed: QsT[d][r]
    {
        int r = t >> 4, d4 = t & 15;
        #pragma unroll
        for (int it = 0; it < 4; it++, r += 16) {
            float4 v = *(const float4*)&g_qkv[(b * SEQ + i0 + r) * NQKV + d4 * 4];
            QsT[(d4 * 4 + 0) * 66 + r] = v.x;
            QsT[(d4 * 4 + 1) * 66 + r] = v.y;
            QsT[(d4 * 4 + 2) * 66 + r] = v.z;
            QsT[(d4 * 4 + 3) * 66 + r] = v.w;
        }
    }

    float o[4][4] = {};
    float m_old[4], l[4];
    #pragma unroll
    for (int i = 0; i < 4; i++) { m_old[i] = -1e30f; l[i] = 0.f; }

    for (int j0 = 0; j0 <= i0; j0 += 64) {
        __syncthreads();   // prior PV reads done (and Q visible on iter 0)

        // Load K (transposed) and V tiles
        {
            int c = t >> 4, d4 = t & 15;
            #pragma unroll
            for (int it = 0; it < 4; it++, c += 16) {
                const float* base = &g_qkv[(b * SEQ + j0 + c) * NQKV];
                float4 kv = *(const float4*)&base[DH + d4 * 4];
                float4 vv = *(const float4*)&base[2 * DH + d4 * 4];
                KsT[(d4 * 4 + 0) * 66 + c] = kv.x;
                KsT[(d4 * 4 + 1) * 66 + c] = kv.y;
                KsT[(d4 * 4 + 2) * 66 + c] = kv.z;
                KsT[(d4 * 4 + 3) * 66 + c] = kv.w;
                *(float2*)&Vs[c * 68 + d4 * 4]     = make_float2(vv.x, vv.y);
                *(float2*)&Vs[c * 68 + d4 * 4 + 2] = make_float2(vv.z, vv.w);
            }
        }
        __syncthreads();

        // S = Q K^T (64x64), 4x4 per thread
        float s[4][4] = {};
        #pragma unroll 4
        for (int d = 0; d < 64; d++) {
            float2 a0 = *(const float2*)&QsT[d * 66 + 2 * ty];
            float2 a1 = *(const float2*)&QsT[d * 66 + 2 * ty + 32];
            float2 b0 = *(const float2*)&KsT[d * 66 + 2 * tx];
            float2 b1 = *(const float2*)&KsT[d * 66 + 2 * tx + 32];
            float a[4]  = {a0.x, a0.y, a1.x, a1.y};
            float bb[4] = {b0.x, b0.y, b1.x, b1.y};
            #pragma unroll
            for (int i = 0; i < 4; i++)
                #pragma unroll
                for (int j = 0; j < 4; j++)
                    s[i][j] += a[i] * bb[j];
        }

        const bool diag = (j0 == i0);
        #pragma unroll
        for (int i = 0; i < 4; i++) {
            int r = 2 * ty + (i & 1) + 32 * (i >> 1);
            #pragma unroll
            for (int j = 0; j < 4; j++) {
                int c = 2 * tx + (j & 1) + 32 * (j >> 1);
                s[i][j] *= scale;
                if (diag && c > r) s[i][j] = -1e30f;
            }
        }

        // Online softmax update
        float p[4][4];
        #pragma unroll
        for (int i = 0; i < 4; i++) {
            float mx = fmaxf(fmaxf(s[i][0], s[i][1]), fmaxf(s[i][2], s[i][3]));
            mx = redmax16(mx);
            float mn = fmaxf(m_old[i], mx);
            float alpha = __expf(m_old[i] - mn);
            float rs = 0.f;
            #pragma unroll
            for (int j = 0; j < 4; j++) { p[i][j] = __expf(s[i][j] - mn); rs += p[i][j]; }
            rs = redsum16(rs);
            l[i] = l[i] * alpha + rs;
            #pragma unroll
            for (int j = 0; j < 4; j++) o[i][j] *= alpha;
            m_old[i] = mn;
        }

        __syncthreads();   // all KsT reads done before overwrite with P
        // Store P transposed: PsT[c][r] (into KsT buffer)
        #pragma unroll
        for (int i = 0; i < 4; i++) {
            int r = 2 * ty + (i & 1) + 32 * (i >> 1);
            #pragma unroll
            for (int j = 0; j < 4; j++) {
                int c = 2 * tx + (j & 1) + 32 * (j >> 1);
                KsT[c * 66 + r] = p[i][j];
            }
        }
        __syncthreads();

        // O += P V
        #pragma unroll 4
        for (int c = 0; c < 64; c++) {
            float2 a0 = *(const float2*)&KsT[c * 66 + 2 * ty];
            float2 a1 = *(const float2*)&KsT[c * 66 + 2 * ty + 32];
            float2 b0 = *(const float2*)&Vs[c * 68 + 2 * tx];
            float2 b1 = *(const float2*)&Vs[c * 68 + 2 * tx + 32];
            float a[4]  = {a0.x, a0.y, a1.x, a1.y};
            float bb[4] = {b0.x, b0.y, b1.x, b1.y};
            #pragma unroll
            for (int i = 0; i < 4; i++)
                #pragma unroll
                for (int j = 0; j < 4; j++)
                    o[i][j] += a[i] * bb[j];
        }
    }

    // Finalize: O /= l, write [row][64]
    #pragma unroll
    for (int i = 0; i < 4; i++) {
        float inv = 1.0f / l[i];
        int r = b * SEQ + i0 + 2 * ty + (i & 1) + 32 * (i >> 1);
        *(float2*)&g_attn[r * DH + 2 * tx]      = make_float2(o[i][0] * inv, o[i][1] * inv);
        *(float2*)&g_attn[r * DH + 2 * tx + 32] = make_float2(o[i][2] * inv, o[i][3] * inv);
    }
}

// ---------------------------------------------------------------------------
// Kernel C: out = attn @ W_out + b_out  (M=16384, K=64, N=512)
// ---------------------------------------------------------------------------
__global__ __launch_bounds__(256) void out_gemm_kernel(
    const float* __restrict__ w, const float* __restrict__ bias,
    float* __restrict__ out)
{
    __shared__ float AsT[64 * 66];  // [k][m]
    __shared__ float Bs[64 * 68];   // [k][n]

    const int t  = threadIdx.x;
    const int tx = t & 15, ty = t >> 4;
    const int m0 = blockIdx.x * 64;
    const int n0 = blockIdx.y * 64;

    {
        int r = t >> 4, d4 = t & 15;
        #pragma unroll
        for (int it = 0; it < 4; it++, r += 16) {
            float4 v = *(const float4*)&g_attn[(m0 + r) * DH + d4 * 4];
            AsT[(d4 * 4 + 0) * 66 + r] = v.x;
            AsT[(d4 * 4 + 1) * 66 + r] = v.y;
            AsT[(d4 * 4 + 2) * 66 + r] = v.z;
            AsT[(d4 * 4 + 3) * 66 + r] = v.w;
        }
        int k = t >> 4, n4 = t & 15;
        #pragma unroll
        for (int it = 0; it < 4; it++, k += 16) {
            float4 v = *(const float4*)&w[k * DOUT + n0 + n4 * 4];
            *(float4*)&Bs[k * 68 + n4 * 4] = v;
        }
    }
    __syncthreads();

    float acc[4][4] = {};
    #pragma unroll 4
    for (int k = 0; k < 64; k++) {
        float2 a0 = *(const float2*)&AsT[k * 66 + 2 * ty];
        float2 a1 = *(const float2*)&AsT[k * 66 + 2 * ty + 32];
        float2 b0 = *(const float2*)&Bs[k * 68 + 2 * tx];
        float2 b1 = *(const float2*)&Bs[k * 68 + 2 * tx + 32];
        float a[4]  = {a0.x, a0.y, a1.x, a1.y};
        float bb[4] = {b0.x, b0.y, b1.x, b1.y};
        #pragma unroll
        for (int i = 0; i < 4; i++)
            #pragma unroll
            for (int j = 0; j < 4; j++)
                acc[i][j] += a[i] * bb[j];
    }

    #pragma unroll
    for (int i = 0; i < 4; i++) {
        int r = m0 + 2 * ty + (i & 1) + 32 * (i >> 1);
        int c0 = n0 + 2 * tx;
        float2 v0 = make_float2(acc[i][0] + bias[c0],      acc[i][1] + bias[c0 + 1]);
        float2 v1 = make_float2(acc[i][2] + bias[c0 + 32], acc[i][3] + bias[c0 + 33]);
        *(float2*)&out[r * DOUT + c0]      = v0;
        *(float2*)&out[r * DOUT + c0 + 32] = v1;
    }
}

// ---------------------------------------------------------------------------
extern "C" void kernel_launch(void* const* d_in, const int* in_sizes, int n_in,
                              void* d_out, int out_size)
{
    const float* x    = (const float*)d_in[0];
    const float* Wqkv = (const float*)d_in[1];
    const float* Wout = (const float*)d_in[2];
    const float* bout = (const float*)d_in[3];
    float* out = (float*)d_out;

    qkv_gemm_kernel<<<dim3(MTOT / 64, NQKV / 64), 256>>>(x, Wqkv);

    const int attn_smem = ATTN_SMEM_FLOATS * (int)sizeof(float);  // 51200 B
    cudaFuncSetAttribute(attn_kernel, cudaFuncAttributeMaxDynamicSharedMemorySize, attn_smem);
    attn_kernel<<<dim3(SEQ / 64, NB), 256, attn_smem>>>();

    out_gemm_kernel<<<dim3(MTOT / 64, DOUT / 64), 256>>>(Wout, bout, out);
}

// round 2
// speedup vs baseline: 2.1808x; 2.1808x over previous
#include <cuda_runtime.h>
#include <cuda_bf16.h>

#define SEQ   4096
#define NB    4
#define TOK   (NB * SEQ)   // 16384
#define DIN   512
#define DH    64
#define DOUT  512

// ---------------------------------------------------------------------------
// Device scratch (allocation-free rule). All bf16 data stored as packed u32
// words: word w of a row holds elements (2w, 2w+1) along the k dimension.
// ---------------------------------------------------------------------------
__device__ unsigned g_x_hi[TOK * (DIN/2)];     // [16384][256]
__device__ unsigned g_x_lo[TOK * (DIN/2)];
__device__ unsigned g_wqkvT_hi[192 * (DIN/2)]; // [n=192][kword=256]
__device__ unsigned g_wqkvT_lo[192 * (DIN/2)];
__device__ unsigned g_woT_hi[DOUT * (DH/2)];   // [n=512][kword=32]
__device__ unsigned g_woT_lo[DOUT * (DH/2)];
__device__ unsigned g_q_hi[TOK * (DH/2)];      // [token][32]
__device__ unsigned g_q_lo[TOK * (DH/2)];
__device__ unsigned g_k_hi[TOK * (DH/2)];
__device__ unsigned g_k_lo[TOK * (DH/2)];
__device__ unsigned short g_vT_hi[NB * DH * SEQ];  // [b][d][s]
__device__ unsigned short g_vT_lo[NB * DH * SEQ];
__device__ unsigned g_attn_hi[TOK * (DH/2)];
__device__ unsigned g_attn_lo[TOK * (DH/2)];

// ---------------------------------------------------------------------------
// Helpers
// ---------------------------------------------------------------------------
__device__ __forceinline__ void split2(float x0, float x1, unsigned &h, unsigned &l) {
    __nv_bfloat162 hh = __floats2bfloat162_rn(x0, x1);   // .x = x0 (low half)
    h = *reinterpret_cast<unsigned*>(&hh);
    float r0 = x0 - __bfloat162float(hh.x);
    float r1 = x1 - __bfloat162float(hh.y);
    __nv_bfloat162 ll = __floats2bfloat162_rn(r0, r1);
    l = *reinterpret_cast<unsigned*>(&ll);
}

__device__ __forceinline__ void split1(float x, unsigned short &h, unsigned short &l) {
    __nv_bfloat16 hb = __float2bfloat16(x);
    h = *reinterpret_cast<unsigned short*>(&hb);
    __nv_bfloat16 lb = __float2bfloat16(x - __bfloat162float(hb));
    l = *reinterpret_cast<unsigned short*>(&lb);
}

#define MMA16816(c, a0, a1, a2, a3, b0, b1)                                   \
    asm volatile(                                                             \
        "mma.sync.aligned.m16n8k16.row.col.f32.bf16.bf16.f32 "                \
        "{%0,%1,%2,%3}, {%4,%5,%6,%7}, {%8,%9}, {%0,%1,%2,%3};\n"             \
        : "+f"((c)[0]), "+f"((c)[1]), "+f"((c)[2]), "+f"((c)[3])              \
        : "r"(a0), "r"(a1), "r"(a2), "r"(a3), "r"(b0), "r"(b1))

// smem row stride in u32 words (d=64 -> 32 data words + 4 pad => conflict-free)
#define SRS 36

// ---------------------------------------------------------------------------
// Prep kernels: split inputs into hi/lo bf16
// ---------------------------------------------------------------------------
__global__ __launch_bounds__(256) void prep_x_kernel(const float* __restrict__ x) {
    int idx0 = blockIdx.x * 1024 + threadIdx.x;
    #pragma unroll
    for (int it = 0; it < 4; it++) {
        int i = idx0 + it * 256;           // word index, total TOK*256 = 4194304
        float2 v = *(const float2*)(x + (size_t)i * 2);
        unsigned h, l; split2(v.x, v.y, h, l);
        g_x_hi[i] = h; g_x_lo[i] = l;
    }
}

__global__ __launch_bounds__(256) void prep_wqkv_kernel(const float* __restrict__ w) {
    // W_qkv [512][192] -> transposed split [192][256 words]
    int n = blockIdx.x;          // 0..191
    int kw = threadIdx.x;        // 0..255
    float a = w[(size_t)(2 * kw) * 192 + n];
    float b = w[(size_t)(2 * kw + 1) * 192 + n];
    unsigned h, l; split2(a, b, h, l);
    g_wqkvT_hi[n * 256 + kw] = h; g_wqkvT_lo[n * 256 + kw] = l;
}

__global__ __launch_bounds__(256) void prep_wout_kernel(const float* __restrict__ w) {
    // W_out [64][512] -> transposed split [512][32 words]
    int idx = blockIdx.x * 256 + threadIdx.x;   // 0..16383
    int n = idx >> 5, kw = idx & 31;
    float a = w[(size_t)(2 * kw) * DOUT + n];
    float b = w[(size_t)(2 * kw + 1) * DOUT + n];
    unsigned h, l; split2(a, b, h, l);
    g_woT_hi[n * 32 + kw] = h; g_woT_lo[n * 32 + kw] = l;
}

// ---------------------------------------------------------------------------
// K1: qkv = x @ W_qkv, emulated fp32 via 3x bf16 MMA.
// Block: 128 thr (4 warps), tile M=64 (warp m16), N=64 (one qkv third), K chunks 64.
// n-block 0 -> Q, 1 -> K (row-major split), 2 -> V (transposed split).
// ---------------------------------------------------------------------------
__global__ __launch_bounds__(128) void qkv_mma_kernel() {
    __shared__ __align__(16) unsigned Xh[64 * SRS], Xl[64 * SRS];
    __shared__ __align__(16) unsigned Wh[64 * SRS], Wl[64 * SRS];

    const int t = threadIdx.x, lane = t & 31, warp = t >> 5;
    const int g = lane >> 2, tg = lane & 3;
    const int m0 = blockIdx.x * 64;
    const int nb = blockIdx.y;
    const unsigned* wT_hi = g_wqkvT_hi + (size_t)(nb * 64) * 256;
    const unsigned* wT_lo = g_wqkvT_lo + (size_t)(nb * 64) * 256;

    float c[8][4] = {};

    for (int kc = 0; kc < 8; kc++) {
        __syncthreads();
        for (int i = t; i < 512; i += 128) {
            int r = i >> 3, w4 = (i & 7) * 4;
            *(float4*)(Xh + r * SRS + w4) = *(const float4*)(g_x_hi + (size_t)(m0 + r) * 256 + kc * 32 + w4);
            *(float4*)(Xl + r * SRS + w4) = *(const float4*)(g_x_lo + (size_t)(m0 + r) * 256 + kc * 32 + w4);
            *(float4*)(Wh + r * SRS + w4) = *(const float4*)(wT_hi + (size_t)r * 256 + kc * 32 + w4);
            *(float4*)(Wl + r * SRS + w4) = *(const float4*)(wT_lo + (size_t)r * 256 + kc * 32 + w4);
        }
        __syncthreads();

        #pragma unroll
        for (int kt = 0; kt < 4; kt++) {
            const int r0 = (16 * warp + g) * SRS + kt * 8 + tg;
            const int r1 = (16 * warp + g + 8) * SRS + kt * 8 + tg;
            unsigned ah0 = Xh[r0], ah1 = Xh[r1], ah2 = Xh[r0 + 4], ah3 = Xh[r1 + 4];
            unsigned al0 = Xl[r0], al1 = Xl[r1], al2 = Xl[r0 + 4], al3 = Xl[r1 + 4];
            #pragma unroll
            for (int nt = 0; nt < 8; nt++) {
                const int b0i = (8 * nt + g) * SRS + kt * 8 + tg;
                unsigned bh0 = Wh[b0i], bh1 = Wh[b0i + 4];
                unsigned bl0 = Wl[b0i], bl1 = Wl[b0i + 4];
                MMA16816(c[nt], ah0, ah1, ah2, ah3, bh0, bh1);
                MMA16816(c[nt], ah0, ah1, ah2, ah3, bl0, bl1);
                MMA16816(c[nt], al0, al1, al2, al3, bh0, bh1);
            }
        }
    }

    const int row0 = m0 + 16 * warp + g;
    if (nb < 2) {
        unsigned* oh = nb ? g_k_hi : g_q_hi;
        unsigned* ol = nb ? g_k_lo : g_q_lo;
        #pragma unroll
        for (int nt = 0; nt < 8; nt++) {
            unsigned h, l;
            split2(c[nt][0], c[nt][1], h, l);
            oh[(size_t)row0 * 32 + 4 * nt + tg] = h;
            ol[(size_t)row0 * 32 + 4 * nt + tg] = l;
            split2(c[nt][2], c[nt][3], h, l);
            oh[(size_t)(row0 + 8) * 32 + 4 * nt + tg] = h;
            ol[(size_t)(row0 + 8) * 32 + 4 * nt + tg] = l;
        }
    } else {
        const int b = row0 >> 12, s = row0 & 4095;
        #pragma unroll
        for (int nt = 0; nt < 8; nt++) {
            #pragma unroll
            for (int e = 0; e < 4; e++) {
                int d = 8 * nt + 2 * tg + (e & 1);
                int ss = s + (e >= 2 ? 8 : 0);
                unsigned short h, l; split1(c[nt][e], h, l);
                size_t a = (size_t)(b * DH + d) * SEQ + ss;
                g_vT_hi[a] = h; g_vT_lo[a] = l;
            }
        }
    }
}

// ---------------------------------------------------------------------------
// K2: causal flash attention, Br=Bc=64, 128 thr (warp tile m16 x n64).
// S and P stay in registers (C-frag layout == A-frag layout for PV).
// ---------------------------------------------------------------------------
__global__ __launch_bounds__(128) void attn_mma_kernel() {
    extern __shared__ __align__(16) unsigned sm2[];
    unsigned* Qh = sm2;
    unsigned* Ql = Qh + 64 * SRS;
    unsigned* Kh = Ql + 64 * SRS;
    unsigned* Kl = Kh + 64 * SRS;
    unsigned* Vh = Kl + 64 * SRS;
    unsigned* Vl = Vh + 64 * SRS;

    const int t = threadIdx.x, lane = t & 31, warp = t >> 5;
    const int g = lane >> 2, tg = lane & 3;
    const int b = blockIdx.y;
    const int ib = gridDim.x - 1 - blockIdx.x;   // longest blocks first
    const int i0 = ib * 64;

    // Load Q tile (split)
    for (int i = t; i < 512; i += 128) {
        int r = i >> 3, w4 = (i & 7) * 4;
        *(float4*)(Qh + r * SRS + w4) = *(const float4*)(g_q_hi + (size_t)(b * SEQ + i0 + r) * 32 + w4);
        *(float4*)(Ql + r * SRS + w4) = *(const float4*)(g_q_lo + (size_t)(b * SEQ + i0 + r) * 32 + w4);
    }

    float o[8][4] = {};
    float mrow[2] = {-1e30f, -1e30f};
    float lrow[2] = {0.f, 0.f};

    for (int j0 = 0; j0 <= i0; j0 += 64) {
        __syncthreads();
        for (int i = t; i < 512; i += 128) {
            int r = i >> 3, w4 = (i & 7) * 4;
            *(float4*)(Kh + r * SRS + w4) = *(const float4*)(g_k_hi + (size_t)(b * SEQ + j0 + r) * 32 + w4);
            *(float4*)(Kl + r * SRS + w4) = *(const float4*)(g_k_lo + (size_t)(b * SEQ + j0 + r) * 32 + w4);
            const unsigned* vh = (const unsigned*)g_vT_hi + (size_t)(b * DH + r) * (SEQ / 2) + (j0 >> 1) + w4;
            const unsigned* vl = (const unsigned*)g_vT_lo + (size_t)(b * DH + r) * (SEQ / 2) + (j0 >> 1) + w4;
            *(float4*)(Vh + r * SRS + w4) = *(const float4*)vh;
            *(float4*)(Vl + r * SRS + w4) = *(const float4*)vl;
        }
        __syncthreads();

        // ---- S = Q K^T (scaled later) ----
        float c[8][4] = {};
        #pragma unroll
        for (int kt = 0; kt < 4; kt++) {
            const int r0 = (16 * warp + g) * SRS + kt * 8 + tg;
            const int r1 = (16 * warp + g + 8) * SRS + kt * 8 + tg;
            unsigned ah0 = Qh[r0], ah1 = Qh[r1], ah2 = Qh[r0 + 4], ah3 = Qh[r1 + 4];
            unsigned al0 = Ql[r0], al1 = Ql[r1], al2 = Ql[r0 + 4], al3 = Ql[r1 + 4];
            #pragma unroll
            for (int nt = 0; nt < 8; nt++) {
                const int b0i = (8 * nt + g) * SRS + kt * 8 + tg;
                unsigned bh0 = Kh[b0i], bh1 = Kh[b0i + 4];
                unsigned bl0 = Kl[b0i], bl1 = Kl[b0i + 4];
                MMA16816(c[nt], ah0, ah1, ah2, ah3, bh0, bh1);
                MMA16816(c[nt], ah0, ah1, ah2, ah3, bl0, bl1);
                MMA16816(c[nt], al0, al1, al2, al3, bh0, bh1);
            }
        }

        // ---- scale + causal mask ----
        const bool diag = (j0 == i0);
        #pragma unroll
        for (int nt = 0; nt < 8; nt++) {
            #pragma unroll
            for (int e = 0; e < 4; e++) {
                int row = 16 * warp + g + (e >= 2 ? 8 : 0);
                int col = 8 * nt + 2 * tg + (e & 1);
                c[nt][e] *= 0.125f;
                if (diag && col > row) c[nt][e] = -1e30f;
            }
        }

        // ---- online softmax (rows g and g+8) ----
        float mx0 = -1e30f, mx1 = -1e30f;
        #pragma unroll
        for (int nt = 0; nt < 8; nt++) {
            mx0 = fmaxf(mx0, fmaxf(c[nt][0], c[nt][1]));
            mx1 = fmaxf(mx1, fmaxf(c[nt][2], c[nt][3]));
        }
        mx0 = fmaxf(mx0, __shfl_xor_sync(0xffffffffu, mx0, 1));
        mx0 = fmaxf(mx0, __shfl_xor_sync(0xffffffffu, mx0, 2));
        mx1 = fmaxf(mx1, __shfl_xor_sync(0xffffffffu, mx1, 1));
        mx1 = fmaxf(mx1, __shfl_xor_sync(0xffffffffu, mx1, 2));
        float mn0 = fmaxf(mrow[0], mx0), mn1 = fmaxf(mrow[1], mx1);
        float a0 = __expf(mrow[0] - mn0), a1 = __expf(mrow[1] - mn1);
        mrow[0] = mn0; mrow[1] = mn1;

        float s0 = 0.f, s1 = 0.f;
        #pragma unroll
        for (int nt = 0; nt < 8; nt++) {
            c[nt][0] = __expf(c[nt][0] - mn0); s0 += c[nt][0];
            c[nt][1] = __expf(c[nt][1] - mn0); s0 += c[nt][1];
            c[nt][2] = __expf(c[nt][2] - mn1); s1 += c[nt][2];
            c[nt][3] = __expf(c[nt][3] - mn1); s1 += c[nt][3];
        }
        s0 += __shfl_xor_sync(0xffffffffu, s0, 1);
        s0 += __shfl_xor_sync(0xffffffffu, s0, 2);
        s1 += __shfl_xor_sync(0xffffffffu, s1, 1);
        s1 += __shfl_xor_sync(0xffffffffu, s1, 2);
        lrow[0] = lrow[0] * a0 + s0;
        lrow[1] = lrow[1] * a1 + s1;
        #pragma unroll
        for (int nt = 0; nt < 8; nt++) {
            o[nt][0] *= a0; o[nt][1] *= a0; o[nt][2] *= a1; o[nt][3] *= a1;
        }

        // ---- O += P V : P fragments straight from c regs ----
        #pragma unroll
        for (int kt = 0; kt < 4; kt++) {
            unsigned ah0, al0, ah1, al1, ah2, al2, ah3, al3;
            split2(c[2 * kt][0], c[2 * kt][1], ah0, al0);
            split2(c[2 * kt][2], c[2 * kt][3], ah1, al1);
            split2(c[2 * kt + 1][0], c[2 * kt + 1][1], ah2, al2);
            split2(c[2 * kt + 1][2], c[2 * kt + 1][3], ah3, al3);
            #pragma unroll
            for (int nt = 0; nt < 8; nt++) {
                const int b0i = (8 * nt + g) * SRS + kt * 8 + tg;
                unsigned bh0 = Vh[b0i], bh1 = Vh[b0i + 4];
                unsigned bl0 = Vl[b0i], bl1 = Vl[b0i + 4];
                MMA16816(o[nt], ah0, ah1, ah2, ah3, bh0, bh1);
                MMA16816(o[nt], ah0, ah1, ah2, ah3, bl0, bl1);
                MMA16816(o[nt], al0, al1, al2, al3, bh0, bh1);
            }
        }
    }

    // ---- finalize: O /= l, write split bf16 ----
    float inv0 = 1.0f / lrow[0], inv1 = 1.0f / lrow[1];
    const int tok = b * SEQ + i0 + 16 * warp + g;
    #pragma unroll
    for (int nt = 0; nt < 8; nt++) {
        unsigned h, l;
        split2(o[nt][0] * inv0, o[nt][1] * inv0, h, l);
        g_attn_hi[(size_t)tok * 32 + 4 * nt + tg] = h;
        g_attn_lo[(size_t)tok * 32 + 4 * nt + tg] = l;
        split2(o[nt][2] * inv1, o[nt][3] * inv1, h, l);
        g_attn_hi[(size_t)(tok + 8) * 32 + 4 * nt + tg] = h;
        g_attn_lo[(size_t)(tok + 8) * 32 + 4 * nt + tg] = l;
    }
}

// ---------------------------------------------------------------------------
// K3: out = attn @ W_out + b_out  (M=16384, K=64, N=512)
// ---------------------------------------------------------------------------
__global__ __launch_bounds__(128) void out_mma_kernel(
    const float* __restrict__ bias, float* __restrict__ out)
{
    __shared__ __align__(16) unsigned Ah[64 * SRS], Al[64 * SRS];
    __shared__ __align__(16) unsigned Bh[64 * SRS], Bl[64 * SRS];

    const int t = threadIdx.x, lane = t & 31, warp = t >> 5;
    const int g = lane >> 2, tg = lane & 3;
    const int m0 = blockIdx.x * 64;
    const int n0 = blockIdx.y * 64;

    for (int i = t; i < 512; i += 128) {
        int r = i >> 3, w4 = (i & 7) * 4;
        *(float4*)(Ah + r * SRS + w4) = *(const float4*)(g_attn_hi + (size_t)(m0 + r) * 32 + w4);
        *(float4*)(Al + r * SRS + w4) = *(const float4*)(g_attn_lo + (size_t)(m0 + r) * 32 + w4);
        *(float4*)(Bh + r * SRS + w4) = *(const float4*)(g_woT_hi + (size_t)(n0 + r) * 32 + w4);
        *(float4*)(Bl + r * SRS + w4) = *(const float4*)(g_woT_lo + (size_t)(n0 + r) * 32 + w4);
    }
    __syncthreads();

    float c[8][4] = {};
    #pragma unroll
    for (int kt = 0; kt < 4; kt++) {
        const int r0 = (16 * warp + g) * SRS + kt * 8 + tg;
        const int r1 = (16 * warp + g + 8) * SRS + kt * 8 + tg;
        unsigned ah0 = Ah[r0], ah1 = Ah[r1], ah2 = Ah[r0 + 4], ah3 = Ah[r1 + 4];
        unsigned al0 = Al[r0], al1 = Al[r1], al2 = Al[r0 + 4], al3 = Al[r1 + 4];
        #pragma unroll
        for (int nt = 0; nt < 8; nt++) {
            const int b0i = (8 * nt + g) * SRS + kt * 8 + tg;
            unsigned bh0 = Bh[b0i], bh1 = Bh[b0i + 4];
            unsigned bl0 = Bl[b0i], bl1 = Bl[b0i + 4];
            MMA16816(c[nt], ah0, ah1, ah2, ah3, bh0, bh1);
            MMA16816(c[nt], ah0, ah1, ah2, ah3, bl0, bl1);
            MMA16816(c[nt], al0, al1, al2, al3, bh0, bh1);
        }
    }

    const int row = m0 + 16 * warp + g;
    #pragma unroll
    for (int nt = 0; nt < 8; nt++) {
        int col = n0 + 8 * nt + 2 * tg;
        float b0 = bias[col], b1 = bias[col + 1];
        *(float2*)(out + (size_t)row * DOUT + col) = make_float2(c[nt][0] + b0, c[nt][1] + b1);
        *(float2*)(out + (size_t)(row + 8) * DOUT + col) = make_float2(c[nt][2] + b0, c[nt][3] + b1);
    }
}

// ---------------------------------------------------------------------------
extern "C" void kernel_launch(void* const* d_in, const int* in_sizes, int n_in,
                              void* d_out, int out_size)
{
    const float* x    = (const float*)d_in[0];
    const float* Wqkv = (const float*)d_in[1];
    const float* Wout = (const float*)d_in[2];
    const float* bout = (const float*)d_in[3];
    float* out = (float*)d_out;

    prep_x_kernel<<<4096, 256>>>(x);
    prep_wqkv_kernel<<<192, 256>>>(Wqkv);
    prep_wout_kernel<<<64, 256>>>(Wout);

    qkv_mma_kernel<<<dim3(TOK / 64, 3), 128>>>();

    const int attn_smem = 6 * 64 * SRS * (int)sizeof(unsigned);  // 55296 B
    cudaFuncSetAttribute(attn_mma_kernel, cudaFuncAttributeMaxDynamicSharedMemorySize, attn_smem);
    attn_mma_kernel<<<dim3(SEQ / 64, NB), 128, attn_smem>>>();

    out_mma_kernel<<<dim3(TOK / 64, DOUT / 64), 128>>>(bout, out);
}

// round 4
// speedup vs baseline: 2.9851x; 1.3688x over previous
#include <cuda_runtime.h>
#include <cuda_bf16.h>

#define SEQ   4096
#define NB    4
#define TOK   (NB * SEQ)
#define DIN   512
#define DH    64
#define DOUT  512
#define NCHUNK 288                      // split-j chunks per batch (8 groups: 4k(k+1) prefix)
#define SCALE_LOG2E 0.1803368801111f    // 0.125 * log2(e)

// ---------------------------------------------------------------------------
// Device scratch (allocation-free). bf16 pairs packed in u32 words along k.
// ---------------------------------------------------------------------------
__device__ unsigned g_x_hi[TOK * (DIN/2)];
__device__ unsigned g_x_lo[TOK * (DIN/2)];
__device__ unsigned g_wqkvT_hi[192 * (DIN/2)];
__device__ unsigned g_wqkvT_lo[192 * (DIN/2)];
__device__ unsigned g_woT_hi[DOUT * (DH/2)];
__device__ unsigned g_woT_lo[DOUT * (DH/2)];
__device__ unsigned g_q_hi[TOK * (DH/2)];
__device__ unsigned g_q_lo[TOK * (DH/2)];
__device__ unsigned g_k_hi[TOK * (DH/2)];
__device__ unsigned g_k_lo[TOK * (DH/2)];
__device__ unsigned short g_vT_hi[NB * DH * SEQ];   // [b][d][s]
__device__ unsigned short g_vT_lo[NB * DH * SEQ];
__device__ unsigned g_attn_hi[TOK * (DH/2)];
__device__ unsigned g_attn_lo[TOK * (DH/2)];
__device__ float g_part_o[NB * NCHUNK * 64 * 64];   // unnormalized partial O
__device__ float g_part_m[NB * NCHUNK * 64];        // log2-domain row max
__device__ float g_part_l[NB * NCHUNK * 64];        // row sum

// ---------------------------------------------------------------------------
__device__ __forceinline__ void split2(float x0, float x1, unsigned &h, unsigned &l) {
    __nv_bfloat162 hh = __floats2bfloat162_rn(x0, x1);
    h = *reinterpret_cast<unsigned*>(&hh);
    float r0 = x0 - __bfloat162float(hh.x);
    float r1 = x1 - __bfloat162float(hh.y);
    __nv_bfloat162 ll = __floats2bfloat162_rn(r0, r1);
    l = *reinterpret_cast<unsigned*>(&ll);
}
__device__ __forceinline__ void split1(float x, unsigned short &h, unsigned short &l) {
    __nv_bfloat16 hb = __float2bfloat16(x);
    h = *reinterpret_cast<unsigned short*>(&hb);
    __nv_bfloat16 lb = __float2bfloat16(x - __bfloat162float(hb));
    l = *reinterpret_cast<unsigned short*>(&lb);
}

#define MMA16816(c, a0, a1, a2, a3, b0, b1)                                   \
    asm volatile(                                                             \
        "mma.sync.aligned.m16n8k16.row.col.f32.bf16.bf16.f32 "                \
        "{%0,%1,%2,%3}, {%4,%5,%6,%7}, {%8,%9}, {%0,%1,%2,%3};\n"             \
        : "+f"((c)[0]), "+f"((c)[1]), "+f"((c)[2]), "+f"((c)[3])              \
        : "r"(a0), "r"(a1), "r"(a2), "r"(a3), "r"(b0), "r"(b1))

__device__ __forceinline__ void cpa16(unsigned dst, const void* src) {
    asm volatile("cp.async.cg.shared.global [%0], [%1], 16;\n" :: "r"(dst), "l"(src));
}
#define CP_COMMIT asm volatile("cp.async.commit_group;\n" ::: "memory")
#define CP_WAIT0  asm volatile("cp.async.wait_group 0;\n" ::: "memory")

// ---------------------------------------------------------------------------
// Prep kernels
// ---------------------------------------------------------------------------
__global__ __launch_bounds__(256) void prep_x_kernel(const float* __restrict__ x) {
    int i0 = blockIdx.x * 1024 + threadIdx.x;
    #pragma unroll
    for (int it = 0; it < 4; it++) {
        int idx = i0 + it * 256;                 // float4 index
        float4 v = *(const float4*)(x + (size_t)idx * 4);
        unsigned h0, l0, h1, l1;
        split2(v.x, v.y, h0, l0);
        split2(v.z, v.w, h1, l1);
        g_x_hi[2 * idx] = h0; g_x_hi[2 * idx + 1] = h1;
        g_x_lo[2 * idx] = l0; g_x_lo[2 * idx + 1] = l1;
    }
}
__global__ __launch_bounds__(256) void prep_wqkv_kernel(const float* __restrict__ w) {
    int n = blockIdx.x, kw = threadIdx.x;
    float a = w[(size_t)(2 * kw) * 192 + n];
    float b = w[(size_t)(2 * kw + 1) * 192 + n];
    unsigned h, l; split2(a, b, h, l);
    g_wqkvT_hi[n * 256 + kw] = h; g_wqkvT_lo[n * 256 + kw] = l;
}
__global__ __launch_bounds__(256) void prep_wout_kernel(const float* __restrict__ w) {
    int idx = blockIdx.x * 256 + threadIdx.x;
    int n = idx >> 5, kw = idx & 31;
    float a = w[(size_t)(2 * kw) * DOUT + n];
    float b = w[(size_t)(2 * kw + 1) * DOUT + n];
    unsigned h, l; split2(a, b, h, l);
    g_woT_hi[n * 32 + kw] = h; g_woT_lo[n * 32 + kw] = l;
}

// ---------------------------------------------------------------------------
// K1: qkv GEMM. 256 thr, tile M=128 N=64, k-chunks 32, cp.async double-buffer.
// ---------------------------------------------------------------------------
#define QS 20

__global__ __launch_bounds__(256) void qkv_mma_kernel() {
    extern __shared__ __align__(16) unsigned sq[];
    const unsigned sbase = (unsigned)__cvta_generic_to_shared(sq);
    const int t = threadIdx.x, lane = t & 31, warp = t >> 5;
    const int g = lane >> 2, tg = lane & 3;
    const int m0 = blockIdx.x * 128;
    const int nb = blockIdx.y;
    const int rb = (warp & 3) * 32;
    const int cb = (warp >> 2) * 32;

    auto prefetch = [&](int kc, int st) {
        unsigned sb = sbase + st * 7680 * 4;
        #pragma unroll
        for (int i = 0; i < 2; i++) {
            int idx = t + i * 256;
            int r = idx >> 2, j = (idx & 3) * 4;
            cpa16(sb + (r * QS + j) * 4,          g_x_hi + (size_t)(m0 + r) * 256 + kc * 16 + j);
            cpa16(sb + (2560 + r * QS + j) * 4,   g_x_lo + (size_t)(m0 + r) * 256 + kc * 16 + j);
        }
        {
            int r = t >> 2, j = (t & 3) * 4;
            cpa16(sb + (5120 + r * QS + j) * 4,   g_wqkvT_hi + (size_t)(nb * 64 + r) * 256 + kc * 16 + j);
            cpa16(sb + (6400 + r * QS + j) * 4,   g_wqkvT_lo + (size_t)(nb * 64 + r) * 256 + kc * 16 + j);
        }
        CP_COMMIT;
    };

    float c[2][4][4] = {};
    prefetch(0, 0);

    for (int kc = 0; kc < 16; kc++) {
        const int st = kc & 1;
        CP_WAIT0;
        __syncthreads();
        if (kc + 1 < 16) prefetch(kc + 1, st ^ 1);

        const unsigned* Xh = sq + st * 7680;
        const unsigned* Xl = Xh + 2560;
        const unsigned* Wh = Xh + 5120;
        const unsigned* Wl = Xh + 6400;

        #pragma unroll
        for (int kt = 0; kt < 2; kt++) {
            const int w0 = kt * 8 + tg;
            unsigned ah[2][4], al[2][4];
            #pragma unroll
            for (int gm = 0; gm < 2; gm++) {
                const int r0 = (rb + 16 * gm + g) * QS + w0;
                const int r1 = r0 + 8 * QS;
                ah[gm][0] = Xh[r0]; ah[gm][1] = Xh[r1]; ah[gm][2] = Xh[r0 + 4]; ah[gm][3] = Xh[r1 + 4];
                al[gm][0] = Xl[r0]; al[gm][1] = Xl[r1]; al[gm][2] = Xl[r0 + 4]; al[gm][3] = Xl[r1 + 4];
            }
            #pragma unroll
            for (int nt = 0; nt < 4; nt++) {
                const int bi = (cb + 8 * nt + g) * QS + w0;
                unsigned bh0 = Wh[bi], bh1 = Wh[bi + 4];
                unsigned bl0 = Wl[bi], bl1 = Wl[bi + 4];
                #pragma unroll
                for (int gm = 0; gm < 2; gm++) {
                    MMA16816(c[gm][nt], ah[gm][0], ah[gm][1], ah[gm][2], ah[gm][3], bh0, bh1);
                    MMA16816(c[gm][nt], ah[gm][0], ah[gm][1], ah[gm][2], ah[gm][3], bl0, bl1);
                    MMA16816(c[gm][nt], al[gm][0], al[gm][1], al[gm][2], al[gm][3], bh0, bh1);
                }
            }
        }
    }

    const float qs = (nb == 0) ? SCALE_LOG2E : 1.0f;
    if (nb < 2) {
        unsigned* oh = nb ? g_k_hi : g_q_hi;
        unsigned* ol = nb ? g_k_lo : g_q_lo;
        #pragma unroll
        for (int gm = 0; gm < 2; gm++) {
            int row = m0 + rb + 16 * gm + g;
            #pragma unroll
            for (int nt = 0; nt < 4; nt++) {
                int wd = (cb >> 1) + 4 * nt + tg;
                unsigned h, l;
                split2(c[gm][nt][0] * qs, c[gm][nt][1] * qs, h, l);
                oh[(size_t)row * 32 + wd] = h; ol[(size_t)row * 32 + wd] = l;
                split2(c[gm][nt][2] * qs, c[gm][nt][3] * qs, h, l);
                oh[(size_t)(row + 8) * 32 + wd] = h; ol[(size_t)(row + 8) * 32 + wd] = l;
            }
        }
    } else {
        const int b = (m0 + rb) >> 12;
        #pragma unroll
        for (int gm = 0; gm < 2; gm++) {
            int s = (m0 + rb + 16 * gm + g) & 4095;
            #pragma unroll
            for (int nt = 0; nt < 4; nt++) {
                #pragma unroll
                for (int e = 0; e < 4; e++) {
                    int d = cb + 8 * nt + 2 * tg + (e & 1);
                    int ss = s + (e >= 2 ? 8 : 0);
                    unsigned short h, l; split1(c[gm][nt][e], h, l);
                    size_t a = (size_t)(b * DH + d) * SEQ + ss;
                    g_vT_hi[a] = h; g_vT_lo[a] = l;
                }
            }
        }
    }
}

// ---------------------------------------------------------------------------
// K2: split-j causal flash attention. 128 thr, Br=Bc=64, cp.async 2-stage.
// Chunking: row group k (ib in [8k,8k+8)) has k+1 chunks of <=8 j-tiles.
// Prefix P(k)=4k(k+1); NCHUNK = P(8) = 288 per batch. Covers ib 0..63 exactly.
// ---------------------------------------------------------------------------
#define AS 36

__global__ __launch_bounds__(128) void attn_mma_kernel() {
    extern __shared__ __align__(16) unsigned sa[];
    const unsigned sbase = (unsigned)__cvta_generic_to_shared(sa);
    const int t = threadIdx.x, lane = t & 31, warp = t >> 5;
    const int g = lane >> 2, tg = lane & 3;
    const int b = blockIdx.y;
    const int cx = blockIdx.x;

    int k = 0;
    while (cx >= 4 * (k + 1) * (k + 2)) k++;     // group with P(k) <= cx < P(k+1)
    const int u = cx - 4 * k * (k + 1);
    const int ib = 8 * k + u / (k + 1);
    const int ci = u % (k + 1);
    const int nch = k + 1;
    const int jbeg = ci * 8;
    const int jend = min(jbeg + 8, ib + 1);
    const int i0 = ib * 64;

    // Q tile (plain loads; first loop sync covers visibility)
    unsigned* Qh = sa;
    unsigned* Ql = sa + 2304;
    for (int i = t; i < 512; i += 128) {
        int r = i >> 3, j = (i & 7) * 4;
        *(float4*)(Qh + r * AS + j) = *(const float4*)(g_q_hi + (size_t)(b * SEQ + i0 + r) * 32 + j);
        *(float4*)(Ql + r * AS + j) = *(const float4*)(g_q_lo + (size_t)(b * SEQ + i0 + r) * 32 + j);
    }

    auto prefetch = [&](int jt, int st) {
        unsigned sb = sbase + (4608 + st * 9216) * 4;
        #pragma unroll
        for (int i = 0; i < 4; i++) {
            int idx = t + i * 128;
            int r = idx >> 3, j = idx & 7;
            cpa16(sb + (r * AS + 4 * j) * 4,          g_k_hi + (size_t)(b * SEQ + jt * 64 + r) * 32 + 4 * j);
            cpa16(sb + (2304 + r * AS + 4 * j) * 4,   g_k_lo + (size_t)(b * SEQ + jt * 64 + r) * 32 + 4 * j);
            cpa16(sb + (4608 + r * AS + 4 * j) * 4,   g_vT_hi + (size_t)(b * DH + r) * SEQ + jt * 64 + 8 * j);
            cpa16(sb + (6912 + r * AS + 4 * j) * 4,   g_vT_lo + (size_t)(b * DH + r) * SEQ + jt * 64 + 8 * j);
        }
        CP_COMMIT;
    };

    float o[8][4] = {};
    float mrow[2] = {-1e30f, -1e30f};
    float lrow[2] = {0.f, 0.f};

    prefetch(jbeg, 0);

    for (int jt = jbeg; jt < jend; jt++) {
        const int st = (jt - jbeg) & 1;
        CP_WAIT0;
        __syncthreads();
        if (jt + 1 < jend) prefetch(jt + 1, st ^ 1);

        const unsigned* Kh = sa + 4608 + st * 9216;
        const unsigned* Kl = Kh + 2304;
        const unsigned* Vh = Kh + 4608;
        const unsigned* Vl = Kh + 6912;

        float c[8][4] = {};
        #pragma unroll
        for (int kt = 0; kt < 4; kt++) {
            const int w0 = kt * 8 + tg;
            const int r0 = (16 * warp + g) * AS + w0;
            const int r1 = r0 + 8 * AS;
            unsigned ah0 = Qh[r0], ah1 = Qh[r1], ah2 = Qh[r0 + 4], ah3 = Qh[r1 + 4];
            unsigned al0 = Ql[r0], al1 = Ql[r1], al2 = Ql[r0 + 4], al3 = Ql[r1 + 4];
            #pragma unroll
            for (int nt = 0; nt < 8; nt++) {
                const int bi = (8 * nt + g) * AS + w0;
                unsigned bh0 = Kh[bi], bh1 = Kh[bi + 4];
                unsigned bl0 = Kl[bi], bl1 = Kl[bi + 4];
                MMA16816(c[nt], ah0, ah1, ah2, ah3, bh0, bh1);
                MMA16816(c[nt], ah0, ah1, ah2, ah3, bl0, bl1);
                MMA16816(c[nt], al0, al1, al2, al3, bh0, bh1);
            }
        }

        if (jt == ib) {   // diagonal tile: causal mask
            #pragma unroll
            for (int nt = 0; nt < 8; nt++) {
                #pragma unroll
                for (int e = 0; e < 4; e++) {
                    int row = 16 * warp + g + (e >= 2 ? 8 : 0);
                    int col = 8 * nt + 2 * tg + (e & 1);
                    if (col > row) c[nt][e] = -1e30f;
                }
            }
        }

        float mx0 = -1e30f, mx1 = -1e30f;
        #pragma unroll
        for (int nt = 0; nt < 8; nt++) {
            mx0 = fmaxf(mx0, fmaxf(c[nt][0], c[nt][1]));
            mx1 = fmaxf(mx1, fmaxf(c[nt][2], c[nt][3]));
        }
        mx0 = fmaxf(mx0, __shfl_xor_sync(0xffffffffu, mx0, 1));
        mx0 = fmaxf(mx0, __shfl_xor_sync(0xffffffffu, mx0, 2));
        mx1 = fmaxf(mx1, __shfl_xor_sync(0xffffffffu, mx1, 1));
        mx1 = fmaxf(mx1, __shfl_xor_sync(0xffffffffu, mx1, 2));
        float mn0 = fmaxf(mrow[0], mx0), mn1 = fmaxf(mrow[1], mx1);
        float a0 = exp2f(mrow[0] - mn0), a1 = exp2f(mrow[1] - mn1);
        mrow[0] = mn0; mrow[1] = mn1;

        float s0 = 0.f, s1 = 0.f;
        #pragma unroll
        for (int nt = 0; nt < 8; nt++) {
            c[nt][0] = exp2f(c[nt][0] - mn0); s0 += c[nt][0];
            c[nt][1] = exp2f(c[nt][1] - mn0); s0 += c[nt][1];
            c[nt][2] = exp2f(c[nt][2] - mn1); s1 += c[nt][2];
            c[nt][3] = exp2f(c[nt][3] - mn1); s1 += c[nt][3];
        }
        s0 += __shfl_xor_sync(0xffffffffu, s0, 1);
        s0 += __shfl_xor_sync(0xffffffffu, s0, 2);
        s1 += __shfl_xor_sync(0xffffffffu, s1, 1);
        s1 += __shfl_xor_sync(0xffffffffu, s1, 2);
        lrow[0] = lrow[0] * a0 + s0;
        lrow[1] = lrow[1] * a1 + s1;
        #pragma unroll
        for (int nt = 0; nt < 8; nt++) {
            o[nt][0] *= a0; o[nt][1] *= a0; o[nt][2] *= a1; o[nt][3] *= a1;
        }

        #pragma unroll
        for (int kt = 0; kt < 4; kt++) {
            unsigned ah0, al0, ah1, al1, ah2, al2, ah3, al3;
            split2(c[2 * kt][0],     c[2 * kt][1],     ah0, al0);
            split2(c[2 * kt][2],     c[2 * kt][3],     ah1, al1);
            split2(c[2 * kt + 1][0], c[2 * kt + 1][1], ah2, al2);
            split2(c[2 * kt + 1][2], c[2 * kt + 1][3], ah3, al3);
            const int w0 = kt * 8 + tg;
            #pragma unroll
            for (int nt = 0; nt < 8; nt++) {
                const int bi = (8 * nt + g) * AS + w0;
                unsigned bh0 = Vh[bi], bh1 = Vh[bi + 4];
                unsigned bl0 = Vl[bi], bl1 = Vl[bi + 4];
                MMA16816(o[nt], ah0, ah1, ah2, ah3, bh0, bh1);
                MMA16816(o[nt], ah0, ah1, ah2, ah3, bl0, bl1);
                MMA16816(o[nt], al0, al1, al2, al3, bh0, bh1);
            }
        }
    }

    if (nch == 1) {
        float inv0 = 1.0f / lrow[0], inv1 = 1.0f / lrow[1];
        const int tok = b * SEQ + i0 + 16 * warp + g;
        #pragma unroll
        for (int nt = 0; nt < 8; nt++) {
            unsigned h, l;
            split2(o[nt][0] * inv0, o[nt][1] * inv0, h, l);
            g_attn_hi[(size_t)tok * 32 + 4 * nt + tg] = h;
            g_attn_lo[(size_t)tok * 32 + 4 * nt + tg] = l;
            split2(o[nt][2] * inv1, o[nt][3] * inv1, h, l);
            g_attn_hi[(size_t)(tok + 8) * 32 + 4 * nt + tg] = h;
            g_attn_lo[(size_t)(tok + 8) * 32 + 4 * nt + tg] = l;
        }
    } else {
        const int pb = b * NCHUNK + cx;
        const int r0 = 16 * warp + g;
        #pragma unroll
        for (int nt = 0; nt < 8; nt++) {
            int col = 8 * nt + 2 * tg;
            *(float2*)&g_part_o[((size_t)pb * 64 + r0) * 64 + col]     = make_float2(o[nt][0], o[nt][1]);
            *(float2*)&g_part_o[((size_t)pb * 64 + r0 + 8) * 64 + col] = make_float2(o[nt][2], o[nt][3]);
        }
        if (tg == 0) {
            g_part_m[pb * 64 + r0] = mrow[0];     g_part_l[pb * 64 + r0] = lrow[0];
            g_part_m[pb * 64 + r0 + 8] = mrow[1]; g_part_l[pb * 64 + r0 + 8] = lrow[1];
        }
    }
}

// ---------------------------------------------------------------------------
// K2b: merge split-j partials (row blocks ib >= 8; up to 8 chunks each)
// ---------------------------------------------------------------------------
__global__ __launch_bounds__(128) void merge_kernel() {
    const int ib = 8 + blockIdx.x;   // 8..63
    const int b = blockIdx.y;
    const int k = ib >> 3;
    const int nch = k + 1;
    const int cx0 = 4 * k * (k + 1) + (ib - 8 * k) * (k + 1);

    const int t = threadIdx.x;
    const int r = t >> 1, half = t & 1;

    float mc[8], lc[8], wv[8];
    float mstar = -1e30f;
    for (int c = 0; c < nch; c++) {
        mc[c] = g_part_m[(b * NCHUNK + cx0 + c) * 64 + r];
        lc[c] = g_part_l[(b * NCHUNK + cx0 + c) * 64 + r];
        mstar = fmaxf(mstar, mc[c]);
    }
    float lsum = 0.f;
    for (int c = 0; c < nch; c++) { wv[c] = exp2f(mc[c] - mstar); lsum += wv[c] * lc[c]; }
    const float inv = 1.0f / lsum;

    const int tok = b * SEQ + ib * 64 + r;
    #pragma unroll 4
    for (int j = 0; j < 16; j++) {
        int col = half * 32 + 2 * j;
        float a0 = 0.f, a1 = 0.f;
        for (int c = 0; c < nch; c++) {
            float2 v = *(const float2*)&g_part_o[((size_t)(b * NCHUNK + cx0 + c) * 64 + r) * 64 + col];
            a0 += wv[c] * v.x; a1 += wv[c] * v.y;
        }
        unsigned h, l; split2(a0 * inv, a1 * inv, h, l);
        g_attn_hi[(size_t)tok * 32 + half * 16 + j] = h;
        g_attn_lo[(size_t)tok * 32 + half * 16 + j] = l;
    }
}

// ---------------------------------------------------------------------------
// K3: out = attn @ W_out + b_out. 256 thr, tile 128x128, K=64 single stage.
// ---------------------------------------------------------------------------
__global__ __launch_bounds__(256) void out_mma_kernel(
    const float* __restrict__ bias, float* __restrict__ out)
{
    extern __shared__ __align__(16) unsigned so[];
    unsigned* Ah = so;
    unsigned* Al = so + 4608;
    unsigned* Bh = so + 9216;
    unsigned* Bl = so + 13824;

    const int t = threadIdx.x, lane = t & 31, warp = t >> 5;
    const int g = lane >> 2, tg = lane & 3;
    const int m0 = blockIdx.x * 128;
    const int n0 = blockIdx.y * 128;
    const int rb = (warp & 3) * 32;
    const int cbn = (warp >> 2) * 64;

    for (int i = t; i < 1024; i += 256) {
        int r = i >> 3, j = (i & 7) * 4;
        *(float4*)(Ah + r * AS + j) = *(const float4*)(g_attn_hi + (size_t)(m0 + r) * 32 + j);
        *(float4*)(Al + r * AS + j) = *(const float4*)(g_attn_lo + (size_t)(m0 + r) * 32 + j);
        *(float4*)(Bh + r * AS + j) = *(const float4*)(g_woT_hi + (size_t)(n0 + r) * 32 + j);
        *(float4*)(Bl + r * AS + j) = *(const float4*)(g_woT_lo + (size_t)(n0 + r) * 32 + j);
    }
    __syncthreads();

    float c[2][8][4] = {};
    #pragma unroll
    for (int kt = 0; kt < 4; kt++) {
        const int w0 = kt * 8 + tg;
        unsigned ah[2][4], al[2][4];
        #pragma unroll
        for (int gm = 0; gm < 2; gm++) {
            const int r0 = (rb + 16 * gm + g) * AS + w0;
            const int r1 = r0 + 8 * AS;
            ah[gm][0] = Ah[r0]; ah[gm][1] = Ah[r1]; ah[gm][2] = Ah[r0 + 4]; ah[gm][3] = Ah[r1 + 4];
            al[gm][0] = Al[r0]; al[gm][1] = Al[r1]; al[gm][2] = Al[r0 + 4]; al[gm][3] = Al[r1 + 4];
        }
        #pragma unroll
        for (int nt = 0; nt < 8; nt++) {
            const int bi = (cbn + 8 * nt + g) * AS + w0;
            unsigned bh0 = Bh[bi], bh1 = Bh[bi + 4];
            unsigned bl0 = Bl[bi], bl1 = Bl[bi + 4];
            #pragma unroll
            for (int gm = 0; gm < 2; gm++) {
                MMA16816(c[gm][nt], ah[gm][0], ah[gm][1], ah[gm][2], ah[gm][3], bh0, bh1);
                MMA16816(c[gm][nt], ah[gm][0], ah[gm][1], ah[gm][2], ah[gm][3], bl0, bl1);
                MMA16816(c[gm][nt], al[gm][0], al[gm][1], al[gm][2], al[gm][3], bh0, bh1);
            }
        }
    }

    #pragma unroll
    for (int gm = 0; gm < 2; gm++) {
        int row = m0 + rb + 16 * gm + g;
        #pragma unroll
        for (int nt = 0; nt < 8; nt++) {
            int col = n0 + cbn + 8 * nt + 2 * tg;
            float b0 = bias[col], b1 = bias[col + 1];
            *(float2*)(out + (size_t)row * DOUT + col)       = make_float2(c[gm][nt][0] + b0, c[gm][nt][1] + b1);
            *(float2*)(out + (size_t)(row + 8) * DOUT + col) = make_float2(c[gm][nt][2] + b0, c[gm][nt][3] + b1);
        }
    }
}

// ---------------------------------------------------------------------------
extern "C" void kernel_launch(void* const* d_in, const int* in_sizes, int n_in,
                              void* d_out, int out_size)
{
    const float* x    = (const float*)d_in[0];
    const float* Wqkv = (const float*)d_in[1];
    const float* Wout = (const float*)d_in[2];
    const float* bout = (const float*)d_in[3];
    float* out = (float*)d_out;

    prep_x_kernel<<<2048, 256>>>(x);
    prep_wqkv_kernel<<<192, 256>>>(Wqkv);
    prep_wout_kernel<<<64, 256>>>(Wout);

    cudaFuncSetAttribute(qkv_mma_kernel, cudaFuncAttributeMaxDynamicSharedMemorySize, 61440);
    qkv_mma_kernel<<<dim3(TOK / 128, 3), 256, 61440>>>();

    cudaFuncSetAttribute(attn_mma_kernel, cudaFuncAttributeMaxDynamicSharedMemorySize, 92160);
    attn_mma_kernel<<<dim3(NCHUNK, NB), 128, 92160>>>();

    merge_kernel<<<dim3(56, NB), 128>>>();

    cudaFuncSetAttribute(out_mma_kernel, cudaFuncAttributeMaxDynamicSharedMemorySize, 73728);
    out_mma_kernel<<<dim3(TOK / 128, DOUT / 128), 256, 73728>>>(bout, out);
}

// round 5
// speedup vs baseline: 3.1229x; 1.0462x over previous
#include <cuda_runtime.h>
#include <cuda_bf16.h>

#define SEQ   4096
#define NB    4
#define TOK   (NB * SEQ)
#define DIN   512
#define DH    64
#define DOUT  512
#define NCHUNK 144                      // split-j chunks per batch (Br=128)
#define SCALE_LOG2E 0.1803368801111f    // 0.125 * log2(e)

// ---------------------------------------------------------------------------
// Device scratch (allocation-free). bf16 pairs packed in u32 words along k.
// ---------------------------------------------------------------------------
__device__ unsigned g_x_hi[TOK * (DIN/2)];
__device__ unsigned g_x_lo[TOK * (DIN/2)];
__device__ unsigned g_wqkvT_hi[192 * (DIN/2)];
__device__ unsigned g_wqkvT_lo[192 * (DIN/2)];
__device__ unsigned g_woT_hi[DOUT * (DH/2)];
__device__ unsigned g_woT_lo[DOUT * (DH/2)];
__device__ unsigned g_q_hi[TOK * (DH/2)];
__device__ unsigned g_q_lo[TOK * (DH/2)];
__device__ unsigned g_k_hi[TOK * (DH/2)];
__device__ unsigned g_k_lo[TOK * (DH/2)];
__device__ unsigned short g_vT_hi[NB * DH * SEQ];   // [b][d][s]
__device__ unsigned short g_vT_lo[NB * DH * SEQ];
__device__ unsigned g_attn_hi[TOK * (DH/2)];
__device__ unsigned g_attn_lo[TOK * (DH/2)];
__device__ float g_part_o[NB * NCHUNK * 128 * 64];  // unnormalized partial O
__device__ float g_part_m[NB * NCHUNK * 128];       // log2-domain row max
__device__ float g_part_l[NB * NCHUNK * 128];       // row sum

// ---------------------------------------------------------------------------
__device__ __forceinline__ void split2(float x0, float x1, unsigned &h, unsigned &l) {
    __nv_bfloat162 hh = __floats2bfloat162_rn(x0, x1);
    h = *reinterpret_cast<unsigned*>(&hh);
    float r0 = x0 - __bfloat162float(hh.x);
    float r1 = x1 - __bfloat162float(hh.y);
    __nv_bfloat162 ll = __floats2bfloat162_rn(r0, r1);
    l = *reinterpret_cast<unsigned*>(&ll);
}
__device__ __forceinline__ void split1(float x, unsigned short &h, unsigned short &l) {
    __nv_bfloat16 hb = __float2bfloat16(x);
    h = *reinterpret_cast<unsigned short*>(&hb);
    __nv_bfloat16 lb = __float2bfloat16(x - __bfloat162float(hb));
    l = *reinterpret_cast<unsigned short*>(&lb);
}

#define MMA16816(c, a0, a1, a2, a3, b0, b1)                                   \
    asm volatile(                                                             \
        "mma.sync.aligned.m16n8k16.row.col.f32.bf16.bf16.f32 "                \
        "{%0,%1,%2,%3}, {%4,%5,%6,%7}, {%8,%9}, {%0,%1,%2,%3};\n"             \
        : "+f"((c)[0]), "+f"((c)[1]), "+f"((c)[2]), "+f"((c)[3])              \
        : "r"(a0), "r"(a1), "r"(a2), "r"(a3), "r"(b0), "r"(b1))

__device__ __forceinline__ void cpa16(unsigned dst, const void* src) {
    asm volatile("cp.async.cg.shared.global [%0], [%1], 16;\n" :: "r"(dst), "l"(src));
}
#define CP_COMMIT asm volatile("cp.async.commit_group;\n" ::: "memory")
#define CP_WAIT0  asm volatile("cp.async.wait_group 0;\n" ::: "memory")

// ---------------------------------------------------------------------------
// Prep kernels
// ---------------------------------------------------------------------------
__global__ __launch_bounds__(256) void prep_x_kernel(const float* __restrict__ x) {
    int i0 = blockIdx.x * 1024 + threadIdx.x;
    #pragma unroll
    for (int it = 0; it < 4; it++) {
        int idx = i0 + it * 256;
        float4 v = *(const float4*)(x + (size_t)idx * 4);
        unsigned h0, l0, h1, l1;
        split2(v.x, v.y, h0, l0);
        split2(v.z, v.w, h1, l1);
        g_x_hi[2 * idx] = h0; g_x_hi[2 * idx + 1] = h1;
        g_x_lo[2 * idx] = l0; g_x_lo[2 * idx + 1] = l1;
    }
}
__global__ __launch_bounds__(256) void prep_wqkv_kernel(const float* __restrict__ w) {
    int n = blockIdx.x, kw = threadIdx.x;
    float a = w[(size_t)(2 * kw) * 192 + n];
    float b = w[(size_t)(2 * kw + 1) * 192 + n];
    unsigned h, l; split2(a, b, h, l);
    g_wqkvT_hi[n * 256 + kw] = h; g_wqkvT_lo[n * 256 + kw] = l;
}
__global__ __launch_bounds__(256) void prep_wout_kernel(const float* __restrict__ w) {
    int idx = blockIdx.x * 256 + threadIdx.x;
    int n = idx >> 5, kw = idx & 31;
    float a = w[(size_t)(2 * kw) * DOUT + n];
    float b = w[(size_t)(2 * kw + 1) * DOUT + n];
    unsigned h, l; split2(a, b, h, l);
    g_woT_hi[n * 32 + kw] = h; g_woT_lo[n * 32 + kw] = l;
}

// ---------------------------------------------------------------------------
// K1: qkv GEMM. 256 thr, tile M=128 N=64, k-chunks 32, cp.async double-buffer.
// ---------------------------------------------------------------------------
#define QS 20

__global__ __launch_bounds__(256) void qkv_mma_kernel() {
    extern __shared__ __align__(16) unsigned sq[];
    const unsigned sbase = (unsigned)__cvta_generic_to_shared(sq);
    const int t = threadIdx.x, lane = t & 31, warp = t >> 5;
    const int g = lane >> 2, tg = lane & 3;
    const int m0 = blockIdx.x * 128;
    const int nb = blockIdx.y;
    const int rb = (warp & 3) * 32;
    const int cb = (warp >> 2) * 32;

    auto prefetch = [&](int kc, int st) {
        unsigned sb = sbase + st * 7680 * 4;
        #pragma unroll
        for (int i = 0; i < 2; i++) {
            int idx = t + i * 256;
            int r = idx >> 2, j = (idx & 3) * 4;
            cpa16(sb + (r * QS + j) * 4,          g_x_hi + (size_t)(m0 + r) * 256 + kc * 16 + j);
            cpa16(sb + (2560 + r * QS + j) * 4,   g_x_lo + (size_t)(m0 + r) * 256 + kc * 16 + j);
        }
        {
            int r = t >> 2, j = (t & 3) * 4;
            cpa16(sb + (5120 + r * QS + j) * 4,   g_wqkvT_hi + (size_t)(nb * 64 + r) * 256 + kc * 16 + j);
            cpa16(sb + (6400 + r * QS + j) * 4,   g_wqkvT_lo + (size_t)(nb * 64 + r) * 256 + kc * 16 + j);
        }
        CP_COMMIT;
    };

    float c[2][4][4] = {};
    prefetch(0, 0);

    for (int kc = 0; kc < 16; kc++) {
        const int st = kc & 1;
        CP_WAIT0;
        __syncthreads();
        if (kc + 1 < 16) prefetch(kc + 1, st ^ 1);

        const unsigned* Xh = sq + st * 7680;
        const unsigned* Xl = Xh + 2560;
        const unsigned* Wh = Xh + 5120;
        const unsigned* Wl = Xh + 6400;

        #pragma unroll
        for (int kt = 0; kt < 2; kt++) {
            const int w0 = kt * 8 + tg;
            unsigned ah[2][4], al[2][4];
            #pragma unroll
            for (int gm = 0; gm < 2; gm++) {
                const int r0 = (rb + 16 * gm + g) * QS + w0;
                const int r1 = r0 + 8 * QS;
                ah[gm][0] = Xh[r0]; ah[gm][1] = Xh[r1]; ah[gm][2] = Xh[r0 + 4]; ah[gm][3] = Xh[r1 + 4];
                al[gm][0] = Xl[r0]; al[gm][1] = Xl[r1]; al[gm][2] = Xl[r0 + 4]; al[gm][3] = Xl[r1 + 4];
            }
            #pragma unroll
            for (int nt = 0; nt < 4; nt++) {
                const int bi = (cb + 8 * nt + g) * QS + w0;
                unsigned bh0 = Wh[bi], bh1 = Wh[bi + 4];
                unsigned bl0 = Wl[bi], bl1 = Wl[bi + 4];
                #pragma unroll
                for (int gm = 0; gm < 2; gm++) {
                    MMA16816(c[gm][nt], ah[gm][0], ah[gm][1], ah[gm][2], ah[gm][3], bh0, bh1);
                    MMA16816(c[gm][nt], ah[gm][0], ah[gm][1], ah[gm][2], ah[gm][3], bl0, bl1);
                    MMA16816(c[gm][nt], al[gm][0], al[gm][1], al[gm][2], al[gm][3], bh0, bh1);
                }
            }
        }
    }

    const float qs = (nb == 0) ? SCALE_LOG2E : 1.0f;
    if (nb < 2) {
        unsigned* oh = nb ? g_k_hi : g_q_hi;
        unsigned* ol = nb ? g_k_lo : g_q_lo;
        #pragma unroll
        for (int gm = 0; gm < 2; gm++) {
            int row = m0 + rb + 16 * gm + g;
            #pragma unroll
            for (int nt = 0; nt < 4; nt++) {
                int wd = (cb >> 1) + 4 * nt + tg;
                unsigned h, l;
                split2(c[gm][nt][0] * qs, c[gm][nt][1] * qs, h, l);
                oh[(size_t)row * 32 + wd] = h; ol[(size_t)row * 32 + wd] = l;
                split2(c[gm][nt][2] * qs, c[gm][nt][3] * qs, h, l);
                oh[(size_t)(row + 8) * 32 + wd] = h; ol[(size_t)(row + 8) * 32 + wd] = l;
            }
        }
    } else {
        const int b = (m0 + rb) >> 12;
        #pragma unroll
        for (int gm = 0; gm < 2; gm++) {
            int s = (m0 + rb + 16 * gm + g) & 4095;
            #pragma unroll
            for (int nt = 0; nt < 4; nt++) {
                #pragma unroll
                for (int e = 0; e < 4; e++) {
                    int d = cb + 8 * nt + 2 * tg + (e & 1);
                    int ss = s + (e >= 2 ? 8 : 0);
                    unsigned short h, l; split1(c[gm][nt][e], h, l);
                    size_t a = (size_t)(b * DH + d) * SEQ + ss;
                    g_vT_hi[a] = h; g_vT_lo[a] = l;
                }
            }
        }
    }
}

// ---------------------------------------------------------------------------
// K2: split-j causal flash attention. 256 thr (8 warps), Br=128, Bc=64,
// cp.async 2-stage. Row-block ib in [0,32) needs 2ib+2 j-tiles; group
// gr = ib>>2 has gr+1 chunks of <=8 tiles. Prefix P(gr)=2gr(gr+1); NCHUNK=144.
// ---------------------------------------------------------------------------
#define AS 36

__global__ __launch_bounds__(256) void attn_mma_kernel() {
    extern __shared__ __align__(16) unsigned sa[];
    const unsigned sbase = (unsigned)__cvta_generic_to_shared(sa);
    const int t = threadIdx.x, lane = t & 31, warp = t >> 5;
    const int g = lane >> 2, tg = lane & 3;
    const int b = blockIdx.y;
    const int cx = blockIdx.x;

    int gr = 0;
    while (cx >= 2 * (gr + 1) * (gr + 2)) gr++;
    const int u = cx - 2 * gr * (gr + 1);
    const int ib = 4 * gr + u / (gr + 1);
    const int ci = u % (gr + 1);
    const int nch = gr + 1;
    const int jbeg = ci * 8;
    const int jend = min(jbeg + 8, 2 * ib + 2);
    const int i0 = ib * 128;

    // Q tile (plain loads; first loop sync covers visibility): 128 rows
    unsigned* Qh = sa;
    unsigned* Ql = sa + 4608;
    for (int i = t; i < 1024; i += 256) {
        int r = i >> 3, j = (i & 7) * 4;
        *(float4*)(Qh + r * AS + j) = *(const float4*)(g_q_hi + (size_t)(b * SEQ + i0 + r) * 32 + j);
        *(float4*)(Ql + r * AS + j) = *(const float4*)(g_q_lo + (size_t)(b * SEQ + i0 + r) * 32 + j);
    }

    auto prefetch = [&](int jt, int st) {
        unsigned sb = sbase + (9216 + st * 9216) * 4;
        #pragma unroll
        for (int i = 0; i < 2; i++) {
            int idx = t + i * 256;
            int r = idx >> 3, j = idx & 7;
            cpa16(sb + (r * AS + 4 * j) * 4,          g_k_hi + (size_t)(b * SEQ + jt * 64 + r) * 32 + 4 * j);
            cpa16(sb + (2304 + r * AS + 4 * j) * 4,   g_k_lo + (size_t)(b * SEQ + jt * 64 + r) * 32 + 4 * j);
            cpa16(sb + (4608 + r * AS + 4 * j) * 4,   g_vT_hi + (size_t)(b * DH + r) * SEQ + jt * 64 + 8 * j);
            cpa16(sb + (6912 + r * AS + 4 * j) * 4,   g_vT_lo + (size_t)(b * DH + r) * SEQ + jt * 64 + 8 * j);
        }
        CP_COMMIT;
    };

    float o[8][4] = {};
    float mrow[2] = {-1e30f, -1e30f};
    float lrow[2] = {0.f, 0.f};

    prefetch(jbeg, 0);

    for (int jt = jbeg; jt < jend; jt++) {
        const int st = (jt - jbeg) & 1;
        CP_WAIT0;
        __syncthreads();
        if (jt + 1 < jend) prefetch(jt + 1, st ^ 1);

        const unsigned* Kh = sa + 9216 + st * 9216;
        const unsigned* Kl = Kh + 2304;
        const unsigned* Vh = Kh + 4608;
        const unsigned* Vl = Kh + 6912;

        float c[8][4] = {};
        #pragma unroll
        for (int kt = 0; kt < 4; kt++) {
            const int w0 = kt * 8 + tg;
            const int r0 = (16 * warp + g) * AS + w0;
            const int r1 = r0 + 8 * AS;
            unsigned ah0 = Qh[r0], ah1 = Qh[r1], ah2 = Qh[r0 + 4], ah3 = Qh[r1 + 4];
            unsigned al0 = Ql[r0], al1 = Ql[r1], al2 = Ql[r0 + 4], al3 = Ql[r1 + 4];
            #pragma unroll
            for (int nt = 0; nt < 8; nt++) {
                const int bi = (8 * nt + g) * AS + w0;
                unsigned bh0 = Kh[bi], bh1 = Kh[bi + 4];
                unsigned bl0 = Kl[bi], bl1 = Kl[bi + 4];
                MMA16816(c[nt], ah0, ah1, ah2, ah3, bh0, bh1);
                MMA16816(c[nt], ah0, ah1, ah2, ah3, bl0, bl1);
                MMA16816(c[nt], al0, al1, al2, al3, bh0, bh1);
            }
        }

        if (jt >= 2 * ib) {   // partially-masked tiles (last two of the row-block)
            #pragma unroll
            for (int nt = 0; nt < 8; nt++) {
                #pragma unroll
                for (int e = 0; e < 4; e++) {
                    int row = i0 + 16 * warp + g + (e >= 2 ? 8 : 0);
                    int col = jt * 64 + 8 * nt + 2 * tg + (e & 1);
                    if (col > row) c[nt][e] = -1e30f;
                }
            }
        }

        float mx0 = -1e30f, mx1 = -1e30f;
        #pragma unroll
        for (int nt = 0; nt < 8; nt++) {
            mx0 = fmaxf(mx0, fmaxf(c[nt][0], c[nt][1]));
            mx1 = fmaxf(mx1, fmaxf(c[nt][2], c[nt][3]));
        }
        mx0 = fmaxf(mx0, __shfl_xor_sync(0xffffffffu, mx0, 1));
        mx0 = fmaxf(mx0, __shfl_xor_sync(0xffffffffu, mx0, 2));
        mx1 = fmaxf(mx1, __shfl_xor_sync(0xffffffffu, mx1, 1));
        mx1 = fmaxf(mx1, __shfl_xor_sync(0xffffffffu, mx1, 2));
        float mn0 = fmaxf(mrow[0], mx0), mn1 = fmaxf(mrow[1], mx1);
        float a0 = exp2f(mrow[0] - mn0), a1 = exp2f(mrow[1] - mn1);
        mrow[0] = mn0; mrow[1] = mn1;

        float s0 = 0.f, s1 = 0.f;
        #pragma unroll
        for (int nt = 0; nt < 8; nt++) {
            c[nt][0] = exp2f(c[nt][0] - mn0); s0 += c[nt][0];
            c[nt][1] = exp2f(c[nt][1] - mn0); s0 += c[nt][1];
            c[nt][2] = exp2f(c[nt][2] - mn1); s1 += c[nt][2];
            c[nt][3] = exp2f(c[nt][3] - mn1); s1 += c[nt][3];
        }
        s0 += __shfl_xor_sync(0xffffffffu, s0, 1);
        s0 += __shfl_xor_sync(0xffffffffu, s0, 2);
        s1 += __shfl_xor_sync(0xffffffffu, s1, 1);
        s1 += __shfl_xor_sync(0xffffffffu, s1, 2);
        lrow[0] = lrow[0] * a0 + s0;
        lrow[1] = lrow[1] * a1 + s1;
        #pragma unroll
        for (int nt = 0; nt < 8; nt++) {
            o[nt][0] *= a0; o[nt][1] *= a0; o[nt][2] *= a1; o[nt][3] *= a1;
        }

        #pragma unroll
        for (int kt = 0; kt < 4; kt++) {
            unsigned ah0, al0, ah1, al1, ah2, al2, ah3, al3;
            split2(c[2 * kt][0],     c[2 * kt][1],     ah0, al0);
            split2(c[2 * kt][2],     c[2 * kt][3],     ah1, al1);
            split2(c[2 * kt + 1][0], c[2 * kt + 1][1], ah2, al2);
            split2(c[2 * kt + 1][2], c[2 * kt + 1][3], ah3, al3);
            const int w0 = kt * 8 + tg;
            #pragma unroll
            for (int nt = 0; nt < 8; nt++) {
                const int bi = (8 * nt + g) * AS + w0;
                unsigned bh0 = Vh[bi], bh1 = Vh[bi + 4];
                unsigned bl0 = Vl[bi], bl1 = Vl[bi + 4];
                MMA16816(o[nt], ah0, ah1, ah2, ah3, bh0, bh1);
                MMA16816(o[nt], ah0, ah1, ah2, ah3, bl0, bl1);
                MMA16816(o[nt], al0, al1, al2, al3, bh0, bh1);
            }
        }
    }

    if (nch == 1) {
        float inv0 = 1.0f / lrow[0], inv1 = 1.0f / lrow[1];
        const int tok = b * SEQ + i0 + 16 * warp + g;
        #pragma unroll
        for (int nt = 0; nt < 8; nt++) {
            unsigned h, l;
            split2(o[nt][0] * inv0, o[nt][1] * inv0, h, l);
            g_attn_hi[(size_t)tok * 32 + 4 * nt + tg] = h;
            g_attn_lo[(size_t)tok * 32 + 4 * nt + tg] = l;
            split2(o[nt][2] * inv1, o[nt][3] * inv1, h, l);
            g_attn_hi[(size_t)(tok + 8) * 32 + 4 * nt + tg] = h;
            g_attn_lo[(size_t)(tok + 8) * 32 + 4 * nt + tg] = l;
        }
    } else {
        const int pb = b * NCHUNK + cx;
        const int r0 = 16 * warp + g;
        #pragma unroll
        for (int nt = 0; nt < 8; nt++) {
            int col = 8 * nt + 2 * tg;
            *(float2*)&g_part_o[((size_t)pb * 128 + r0) * 64 + col]     = make_float2(o[nt][0], o[nt][1]);
            *(float2*)&g_part_o[((size_t)pb * 128 + r0 + 8) * 64 + col] = make_float2(o[nt][2], o[nt][3]);
        }
        if (tg == 0) {
            g_part_m[pb * 128 + r0] = mrow[0];     g_part_l[pb * 128 + r0] = lrow[0];
            g_part_m[pb * 128 + r0 + 8] = mrow[1]; g_part_l[pb * 128 + r0 + 8] = lrow[1];
        }
    }
}

// ---------------------------------------------------------------------------
// K2b: merge split-j partials (row blocks ib >= 4; up to 8 chunks each)
// ---------------------------------------------------------------------------
__global__ __launch_bounds__(256) void merge_kernel() {
    const int ib = 4 + blockIdx.x;   // 4..31
    const int b = blockIdx.y;
    const int gr = ib >> 2;
    const int nch = gr + 1;
    const int cx0 = 2 * gr * (gr + 1) + (ib - 4 * gr) * (gr + 1);

    const int t = threadIdx.x;
    const int r = t >> 1, half = t & 1;   // r in 0..127

    float mc[8], lc[8], wv[8];
    float mstar = -1e30f;
    for (int c = 0; c < nch; c++) {
        mc[c] = g_part_m[(b * NCHUNK + cx0 + c) * 128 + r];
        lc[c] = g_part_l[(b * NCHUNK + cx0 + c) * 128 + r];
        mstar = fmaxf(mstar, mc[c]);
    }
    float lsum = 0.f;
    for (int c = 0; c < nch; c++) { wv[c] = exp2f(mc[c] - mstar); lsum += wv[c] * lc[c]; }
    const float inv = 1.0f / lsum;

    const int tok = b * SEQ + ib * 128 + r;
    #pragma unroll 4
    for (int j = 0; j < 16; j++) {
        int col = half * 32 + 2 * j;
        float a0 = 0.f, a1 = 0.f;
        for (int c = 0; c < nch; c++) {
            float2 v = *(const float2*)&g_part_o[((size_t)(b * NCHUNK + cx0 + c) * 128 + r) * 64 + col];
            a0 += wv[c] * v.x; a1 += wv[c] * v.y;
        }
        unsigned h, l; split2(a0 * inv, a1 * inv, h, l);
        g_attn_hi[(size_t)tok * 32 + half * 16 + j] = h;
        g_attn_lo[(size_t)tok * 32 + half * 16 + j] = l;
    }
}

// ---------------------------------------------------------------------------
// K3: out = attn @ W_out + b_out. 256 thr, tile 128x128, K=64 single stage.
// ---------------------------------------------------------------------------
__global__ __launch_bounds__(256) void out_mma_kernel(
    const float* __restrict__ bias, float* __restrict__ out)
{
    extern __shared__ __align__(16) unsigned so[];
    unsigned* Ah = so;
    unsigned* Al = so + 4608;
    unsigned* Bh = so + 9216;
    unsigned* Bl = so + 13824;

    const int t = threadIdx.x, lane = t & 31, warp = t >> 5;
    const int g = lane >> 2, tg = lane & 3;
    const int m0 = blockIdx.x * 128;
    const int n0 = blockIdx.y * 128;
    const int rb = (warp & 3) * 32;
    const int cbn = (warp >> 2) * 64;

    for (int i = t; i < 1024; i += 256) {
        int r = i >> 3, j = (i & 7) * 4;
        *(float4*)(Ah + r * AS + j) = *(const float4*)(g_attn_hi + (size_t)(m0 + r) * 32 + j);
        *(float4*)(Al + r * AS + j) = *(const float4*)(g_attn_lo + (size_t)(m0 + r) * 32 + j);
        *(float4*)(Bh + r * AS + j) = *(const float4*)(g_woT_hi + (size_t)(n0 + r) * 32 + j);
        *(float4*)(Bl + r * AS + j) = *(const float4*)(g_woT_lo + (size_t)(n0 + r) * 32 + j);
    }
    __syncthreads();

    float c[2][8][4] = {};
    #pragma unroll
    for (int kt = 0; kt < 4; kt++) {
        const int w0 = kt * 8 + tg;
        unsigned ah[2][4], al[2][4];
        #pragma unroll
        for (int gm = 0; gm < 2; gm++) {
            const int r0 = (rb + 16 * gm + g) * AS + w0;
            const int r1 = r0 + 8 * AS;
            ah[gm][0] = Ah[r0]; ah[gm][1] = Ah[r1]; ah[gm][2] = Ah[r0 + 4]; ah[gm][3] = Ah[r1 + 4];
            al[gm][0] = Al[r0]; al[gm][1] = Al[r1]; al[gm][2] = Al[r0 + 4]; al[gm][3] = Al[r1 + 4];
        }
        #pragma unroll
        for (int nt = 0; nt < 8; nt++) {
            const int bi = (cbn + 8 * nt + g) * AS + w0;
            unsigned bh0 = Bh[bi], bh1 = Bh[bi + 4];
            unsigned bl0 = Bl[bi], bl1 = Bl[bi + 4];
            #pragma unroll
            for (int gm = 0; gm < 2; gm++) {
                MMA16816(c[gm][nt], ah[gm][0], ah[gm][1], ah[gm][2], ah[gm][3], bh0, bh1);
                MMA16816(c[gm][nt], ah[gm][0], ah[gm][1], ah[gm][2], ah[gm][3], bl0, bl1);
                MMA16816(c[gm][nt], al[gm][0], al[gm][1], al[gm][2], al[gm][3], bh0, bh1);
            }
        }
    }

    #pragma unroll
    for (int gm = 0; gm < 2; gm++) {
        int row = m0 + rb + 16 * gm + g;
        #pragma unroll
        for (int nt = 0; nt < 8; nt++) {
            int col = n0 + cbn + 8 * nt + 2 * tg;
            float b0 = bias[col], b1 = bias[col + 1];
            *(float2*)(out + (size_t)row * DOUT + col)       = make_float2(c[gm][nt][0] + b0, c[gm][nt][1] + b1);
            *(float2*)(out + (size_t)(row + 8) * DOUT + col) = make_float2(c[gm][nt][2] + b0, c[gm][nt][3] + b1);
        }
    }
}

// ---------------------------------------------------------------------------
extern "C" void kernel_launch(void* const* d_in, const int* in_sizes, int n_in,
                              void* d_out, int out_size)
{
    const float* x    = (const float*)d_in[0];
    const float* Wqkv = (const float*)d_in[1];
    const float* Wout = (const float*)d_in[2];
    const float* bout = (const float*)d_in[3];
    float* out = (float*)d_out;

    prep_x_kernel<<<2048, 256>>>(x);
    prep_wqkv_kernel<<<192, 256>>>(Wqkv);
    prep_wout_kernel<<<64, 256>>>(Wout);

    cudaFuncSetAttribute(qkv_mma_kernel, cudaFuncAttributeMaxDynamicSharedMemorySize, 61440);
    qkv_mma_kernel<<<dim3(TOK / 128, 3), 256, 61440>>>();

    cudaFuncSetAttribute(attn_mma_kernel, cudaFuncAttributeMaxDynamicSharedMemorySize, 110592);
    attn_mma_kernel<<<dim3(NCHUNK, NB), 256, 110592>>>();

    merge_kernel<<<dim3(28, NB), 256>>>();

    cudaFuncSetAttribute(out_mma_kernel, cudaFuncAttributeMaxDynamicSharedMemorySize, 73728);
    out_mma_kernel<<<dim3(TOK / 128, DOUT / 128), 256, 73728>>>(bout, out);
}

// round 6
// speedup vs baseline: 3.3049x; 1.0583x over previous
#include <cuda_runtime.h>
#include <cuda_bf16.h>

#define SEQ   4096
#define NB    4
#define TOK   (NB * SEQ)
#define DIN   512
#define DH    64
#define DOUT  512
#define NCHUNK 144                      // split-j chunks per batch (Br=128)
#define SCALE_LOG2E 0.1803368801111f    // 0.125 * log2(e)

// ---------------------------------------------------------------------------
// Device scratch (allocation-free). bf16 pairs packed in u32 words along k.
// ---------------------------------------------------------------------------
__device__ unsigned g_x_hi[TOK * (DIN/2)];
__device__ unsigned g_x_lo[TOK * (DIN/2)];
__device__ unsigned g_wqkvT_hi[192 * (DIN/2)];
__device__ unsigned g_wqkvT_lo[192 * (DIN/2)];
__device__ unsigned g_woT_hi[DOUT * (DH/2)];
__device__ unsigned g_woT_lo[DOUT * (DH/2)];
__device__ unsigned g_q_hi[TOK * (DH/2)];
__device__ unsigned g_q_lo[TOK * (DH/2)];
__device__ unsigned g_k_hi[TOK * (DH/2)];
__device__ unsigned g_k_lo[TOK * (DH/2)];
__device__ unsigned short g_vT_hi[NB * DH * SEQ];   // [b][d][s]
__device__ unsigned short g_vT_lo[NB * DH * SEQ];
__device__ unsigned g_attn_hi[TOK * (DH/2)];
__device__ unsigned g_attn_lo[TOK * (DH/2)];
__device__ float g_part_o[NB * NCHUNK * 128 * 64];  // unnormalized partial O
__device__ float g_part_m[NB * NCHUNK * 128];       // log2-domain row max
__device__ float g_part_l[NB * NCHUNK * 128];       // row sum

// ---------------------------------------------------------------------------
__device__ __forceinline__ void split2(float x0, float x1, unsigned &h, unsigned &l) {
    __nv_bfloat162 hh = __floats2bfloat162_rn(x0, x1);
    h = *reinterpret_cast<unsigned*>(&hh);
    float r0 = x0 - __bfloat162float(hh.x);
    float r1 = x1 - __bfloat162float(hh.y);
    __nv_bfloat162 ll = __floats2bfloat162_rn(r0, r1);
    l = *reinterpret_cast<unsigned*>(&ll);
}
__device__ __forceinline__ void split1(float x, unsigned short &h, unsigned short &l) {
    __nv_bfloat16 hb = __float2bfloat16(x);
    h = *reinterpret_cast<unsigned short*>(&hb);
    __nv_bfloat16 lb = __float2bfloat16(x - __bfloat162float(hb));
    l = *reinterpret_cast<unsigned short*>(&lb);
}

#define MMA16816(c, a0, a1, a2, a3, b0, b1)                                   \
    asm volatile(                                                             \
        "mma.sync.aligned.m16n8k16.row.col.f32.bf16.bf16.f32 "                \
        "{%0,%1,%2,%3}, {%4,%5,%6,%7}, {%8,%9}, {%0,%1,%2,%3};\n"             \
        : "+f"((c)[0]), "+f"((c)[1]), "+f"((c)[2]), "+f"((c)[3])              \
        : "r"(a0), "r"(a1), "r"(a2), "r"(a3), "r"(b0), "r"(b1))

#define LDSM4(d0, d1, d2, d3, a)                                              \
    asm volatile("ldmatrix.sync.aligned.m8n8.x4.shared.b16 {%0,%1,%2,%3}, [%4];" \
        : "=r"(d0), "=r"(d1), "=r"(d2), "=r"(d3) : "r"(a))

__device__ __forceinline__ void cpa16(unsigned dst, const void* src) {
    asm volatile("cp.async.cg.shared.global [%0], [%1], 16;\n" :: "r"(dst), "l"(src));
}
#define CP_COMMIT asm volatile("cp.async.commit_group;\n" ::: "memory")
#define CP_WAIT0  asm volatile("cp.async.wait_group 0;\n" ::: "memory")

// ---------------------------------------------------------------------------
// Prep kernels
// ---------------------------------------------------------------------------
__global__ __launch_bounds__(256) void prep_x_kernel(const float* __restrict__ x) {
    int i0 = blockIdx.x * 1024 + threadIdx.x;
    #pragma unroll
    for (int it = 0; it < 4; it++) {
        int idx = i0 + it * 256;
        float4 v = *(const float4*)(x + (size_t)idx * 4);
        unsigned h0, l0, h1, l1;
        split2(v.x, v.y, h0, l0);
        split2(v.z, v.w, h1, l1);
        g_x_hi[2 * idx] = h0; g_x_hi[2 * idx + 1] = h1;
        g_x_lo[2 * idx] = l0; g_x_lo[2 * idx + 1] = l1;
    }
}
__global__ __launch_bounds__(256) void prep_wqkv_kernel(const float* __restrict__ w) {
    int n = blockIdx.x, kw = threadIdx.x;
    float a = w[(size_t)(2 * kw) * 192 + n];
    float b = w[(size_t)(2 * kw + 1) * 192 + n];
    unsigned h, l; split2(a, b, h, l);
    g_wqkvT_hi[n * 256 + kw] = h; g_wqkvT_lo[n * 256 + kw] = l;
}
__global__ __launch_bounds__(256) void prep_wout_kernel(const float* __restrict__ w) {
    int idx = blockIdx.x * 256 + threadIdx.x;
    int n = idx >> 5, kw = idx & 31;
    float a = w[(size_t)(2 * kw) * DOUT + n];
    float b = w[(size_t)(2 * kw + 1) * DOUT + n];
    unsigned h, l; split2(a, b, h, l);
    g_woT_hi[n * 32 + kw] = h; g_woT_lo[n * 32 + kw] = l;
}

// ---------------------------------------------------------------------------
// K1: qkv GEMM. 256 thr, tile M=128 N=64, k-chunks 32, cp.async double-buffer.
// Fragment loads via ldmatrix.x4.
// ---------------------------------------------------------------------------
#define QS 20

__global__ __launch_bounds__(256) void qkv_mma_kernel() {
    extern __shared__ __align__(16) unsigned sq[];
    const unsigned sbase = (unsigned)__cvta_generic_to_shared(sq);
    const int t = threadIdx.x, lane = t & 31, warp = t >> 5;
    const int g = lane >> 2, tg = lane & 3;
    const int rr = lane & 7, tl = lane >> 3;
    const int m0 = blockIdx.x * 128;
    const int nb = blockIdx.y;
    const int rb = (warp & 3) * 32;
    const int cb = (warp >> 2) * 32;

    // ldmatrix per-lane byte offsets within a region
    const unsigned aoff = ((rb + rr + (tl & 1) * 8) * QS + (tl >> 1) * 4) * 4;
    const unsigned boff = ((cb + rr + ((tl >> 1) & 1) * 8) * QS + (tl & 1) * 4) * 4;

    auto prefetch = [&](int kc, int st) {
        unsigned sb = sbase + st * 7680 * 4;
        #pragma unroll
        for (int i = 0; i < 2; i++) {
            int idx = t + i * 256;
            int r = idx >> 2, j = (idx & 3) * 4;
            cpa16(sb + (r * QS + j) * 4,          g_x_hi + (size_t)(m0 + r) * 256 + kc * 16 + j);
            cpa16(sb + (2560 + r * QS + j) * 4,   g_x_lo + (size_t)(m0 + r) * 256 + kc * 16 + j);
        }
        {
            int r = t >> 2, j = (t & 3) * 4;
            cpa16(sb + (5120 + r * QS + j) * 4,   g_wqkvT_hi + (size_t)(nb * 64 + r) * 256 + kc * 16 + j);
            cpa16(sb + (6400 + r * QS + j) * 4,   g_wqkvT_lo + (size_t)(nb * 64 + r) * 256 + kc * 16 + j);
        }
        CP_COMMIT;
    };

    float c[2][4][4] = {};
    prefetch(0, 0);

    for (int kc = 0; kc < 16; kc++) {
        const int st = kc & 1;
        CP_WAIT0;
        __syncthreads();
        if (kc + 1 < 16) prefetch(kc + 1, st ^ 1);

        const unsigned Xb = sbase + st * 7680 * 4;

        #pragma unroll
        for (int kt = 0; kt < 2; kt++) {
            const unsigned ko = kt * 32;   // 8 words
            unsigned ah[2][4], al[2][4];
            LDSM4(ah[0][0], ah[0][1], ah[0][2], ah[0][3], Xb + aoff + ko);
            LDSM4(ah[1][0], ah[1][1], ah[1][2], ah[1][3], Xb + aoff + 16 * QS * 4 + ko);
            LDSM4(al[0][0], al[0][1], al[0][2], al[0][3], Xb + 2560 * 4 + aoff + ko);
            LDSM4(al[1][0], al[1][1], al[1][2], al[1][3], Xb + 2560 * 4 + aoff + 16 * QS * 4 + ko);
            #pragma unroll
            for (int ntp = 0; ntp < 2; ntp++) {
                unsigned bh0, bh1, bh2, bh3, bl0, bl1, bl2, bl3;
                LDSM4(bh0, bh1, bh2, bh3, Xb + 5120 * 4 + boff + ntp * 16 * QS * 4 + ko);
                LDSM4(bl0, bl1, bl2, bl3, Xb + 6400 * 4 + boff + ntp * 16 * QS * 4 + ko);
                #pragma unroll
                for (int gm = 0; gm < 2; gm++) {
                    MMA16816(c[gm][2 * ntp],     ah[gm][0], ah[gm][1], ah[gm][2], ah[gm][3], bh0, bh1);
                    MMA16816(c[gm][2 * ntp],     ah[gm][0], ah[gm][1], ah[gm][2], ah[gm][3], bl0, bl1);
                    MMA16816(c[gm][2 * ntp],     al[gm][0], al[gm][1], al[gm][2], al[gm][3], bh0, bh1);
                    MMA16816(c[gm][2 * ntp + 1], ah[gm][0], ah[gm][1], ah[gm][2], ah[gm][3], bh2, bh3);
                    MMA16816(c[gm][2 * ntp + 1], ah[gm][0], ah[gm][1], ah[gm][2], ah[gm][3], bl2, bl3);
                    MMA16816(c[gm][2 * ntp + 1], al[gm][0], al[gm][1], al[gm][2], al[gm][3], bh2, bh3);
                }
            }
        }
    }

    const float qs = (nb == 0) ? SCALE_LOG2E : 1.0f;
    if (nb < 2) {
        unsigned* oh = nb ? g_k_hi : g_q_hi;
        unsigned* ol = nb ? g_k_lo : g_q_lo;
        #pragma unroll
        for (int gm = 0; gm < 2; gm++) {
            int row = m0 + rb + 16 * gm + g;
            #pragma unroll
            for (int nt = 0; nt < 4; nt++) {
                int wd = (cb >> 1) + 4 * nt + tg;
                unsigned h, l;
                split2(c[gm][nt][0] * qs, c[gm][nt][1] * qs, h, l);
                oh[(size_t)row * 32 + wd] = h; ol[(size_t)row * 32 + wd] = l;
                split2(c[gm][nt][2] * qs, c[gm][nt][3] * qs, h, l);
                oh[(size_t)(row + 8) * 32 + wd] = h; ol[(size_t)(row + 8) * 32 + wd] = l;
            }
        }
    } else {
        const int b = (m0 + rb) >> 12;
        #pragma unroll
        for (int gm = 0; gm < 2; gm++) {
            int s = (m0 + rb + 16 * gm + g) & 4095;
            #pragma unroll
            for (int nt = 0; nt < 4; nt++) {
                #pragma unroll
                for (int e = 0; e < 4; e++) {
                    int d = cb + 8 * nt + 2 * tg + (e & 1);
                    int ss = s + (e >= 2 ? 8 : 0);
                    unsigned short h, l; split1(c[gm][nt][e], h, l);
                    size_t a = (size_t)(b * DH + d) * SEQ + ss;
                    g_vT_hi[a] = h; g_vT_lo[a] = l;
                }
            }
        }
    }
}

// ---------------------------------------------------------------------------
// K2: split-j causal flash attention. 256 thr (8 warps), Br=128, Bc=64,
// cp.async 2-stage, ldmatrix fragment loads.
// ---------------------------------------------------------------------------
#define AS 36

__global__ __launch_bounds__(256) void attn_mma_kernel() {
    extern __shared__ __align__(16) unsigned sa[];
    const unsigned sbase = (unsigned)__cvta_generic_to_shared(sa);
    const int t = threadIdx.x, lane = t & 31, warp = t >> 5;
    const int g = lane >> 2, tg = lane & 3;
    const int rr = lane & 7, tl = lane >> 3;
    const int b = blockIdx.y;
    const int cx = blockIdx.x;

    int gr = 0;
    while (cx >= 2 * (gr + 1) * (gr + 2)) gr++;
    const int u = cx - 2 * gr * (gr + 1);
    const int ib = 4 * gr + u / (gr + 1);
    const int ci = u % (gr + 1);
    const int nch = gr + 1;
    const int jbeg = ci * 8;
    const int jend = min(jbeg + 8, 2 * ib + 2);
    const int i0 = ib * 128;

    // ldmatrix per-lane byte offsets
    const unsigned aoffQ = ((16 * warp + rr + (tl & 1) * 8) * AS + (tl >> 1) * 4) * 4;
    const unsigned boffB = ((rr + ((tl >> 1) & 1) * 8) * AS + (tl & 1) * 4) * 4;

    // Q tile (plain loads; first loop sync covers visibility): 128 rows
    unsigned* Qh = sa;
    unsigned* Ql = sa + 4608;
    for (int i = t; i < 1024; i += 256) {
        int r = i >> 3, j = (i & 7) * 4;
        *(float4*)(Qh + r * AS + j) = *(const float4*)(g_q_hi + (size_t)(b * SEQ + i0 + r) * 32 + j);
        *(float4*)(Ql + r * AS + j) = *(const float4*)(g_q_lo + (size_t)(b * SEQ + i0 + r) * 32 + j);
    }

    auto prefetch = [&](int jt, int st) {
        unsigned sb = sbase + (9216 + st * 9216) * 4;
        #pragma unroll
        for (int i = 0; i < 2; i++) {
            int idx = t + i * 256;
            int r = idx >> 3, j = idx & 7;
            cpa16(sb + (r * AS + 4 * j) * 4,          g_k_hi + (size_t)(b * SEQ + jt * 64 + r) * 32 + 4 * j);
            cpa16(sb + (2304 + r * AS + 4 * j) * 4,   g_k_lo + (size_t)(b * SEQ + jt * 64 + r) * 32 + 4 * j);
            cpa16(sb + (4608 + r * AS + 4 * j) * 4,   g_vT_hi + (size_t)(b * DH + r) * SEQ + jt * 64 + 8 * j);
            cpa16(sb + (6912 + r * AS + 4 * j) * 4,   g_vT_lo + (size_t)(b * DH + r) * SEQ + jt * 64 + 8 * j);
        }
        CP_COMMIT;
    };

    float o[8][4] = {};
    float mrow[2] = {-1e30f, -1e30f};
    float lrow[2] = {0.f, 0.f};

    prefetch(jbeg, 0);

    for (int jt = jbeg; jt < jend; jt++) {
        const int st = (jt - jbeg) & 1;
        CP_WAIT0;
        __syncthreads();
        if (jt + 1 < jend) prefetch(jt + 1, st ^ 1);

        const unsigned KVb = sbase + (9216 + st * 9216) * 4;

        float c[8][4] = {};
        #pragma unroll
        for (int kt = 0; kt < 4; kt++) {
            const unsigned ko = kt * 32;
            unsigned ah0, ah1, ah2, ah3, al0, al1, al2, al3;
            LDSM4(ah0, ah1, ah2, ah3, sbase + aoffQ + ko);
            LDSM4(al0, al1, al2, al3, sbase + 4608 * 4 + aoffQ + ko);
            #pragma unroll
            for (int ntp = 0; ntp < 4; ntp++) {
                unsigned bh0, bh1, bh2, bh3, bl0, bl1, bl2, bl3;
                LDSM4(bh0, bh1, bh2, bh3, KVb + boffB + ntp * 16 * AS * 4 + ko);
                LDSM4(bl0, bl1, bl2, bl3, KVb + 2304 * 4 + boffB + ntp * 16 * AS * 4 + ko);
                MMA16816(c[2 * ntp],     ah0, ah1, ah2, ah3, bh0, bh1);
                MMA16816(c[2 * ntp],     ah0, ah1, ah2, ah3, bl0, bl1);
                MMA16816(c[2 * ntp],     al0, al1, al2, al3, bh0, bh1);
                MMA16816(c[2 * ntp + 1], ah0, ah1, ah2, ah3, bh2, bh3);
                MMA16816(c[2 * ntp + 1], ah0, ah1, ah2, ah3, bl2, bl3);
                MMA16816(c[2 * ntp + 1], al0, al1, al2, al3, bh2, bh3);
            }
        }

        if (jt >= 2 * ib) {   // partially-masked tiles (last two of the row-block)
            #pragma unroll
            for (int nt = 0; nt < 8; nt++) {
                #pragma unroll
                for (int e = 0; e < 4; e++) {
                    int row = i0 + 16 * warp + g + (e >= 2 ? 8 : 0);
                    int col = jt * 64 + 8 * nt + 2 * tg + (e & 1);
                    if (col > row) c[nt][e] = -1e30f;
                }
            }
        }

        float mx0 = -1e30f, mx1 = -1e30f;
        #pragma unroll
        for (int nt = 0; nt < 8; nt++) {
            mx0 = fmaxf(mx0, fmaxf(c[nt][0], c[nt][1]));
            mx1 = fmaxf(mx1, fmaxf(c[nt][2], c[nt][3]));
        }
        mx0 = fmaxf(mx0, __shfl_xor_sync(0xffffffffu, mx0, 1));
        mx0 = fmaxf(mx0, __shfl_xor_sync(0xffffffffu, mx0, 2));
        mx1 = fmaxf(mx1, __shfl_xor_sync(0xffffffffu, mx1, 1));
        mx1 = fmaxf(mx1, __shfl_xor_sync(0xffffffffu, mx1, 2));
        float mn0 = fmaxf(mrow[0], mx0), mn1 = fmaxf(mrow[1], mx1);
        float a0 = exp2f(mrow[0] - mn0), a1 = exp2f(mrow[1] - mn1);
        mrow[0] = mn0; mrow[1] = mn1;

        float s0 = 0.f, s1 = 0.f;
        #pragma unroll
        for (int nt = 0; nt < 8; nt++) {
            c[nt][0] = exp2f(c[nt][0] - mn0); s0 += c[nt][0];
            c[nt][1] = exp2f(c[nt][1] - mn0); s0 += c[nt][1];
            c[nt][2] = exp2f(c[nt][2] - mn1); s1 += c[nt][2];
            c[nt][3] = exp2f(c[nt][3] - mn1); s1 += c[nt][3];
        }
        s0 += __shfl_xor_sync(0xffffffffu, s0, 1);
        s0 += __shfl_xor_sync(0xffffffffu, s0, 2);
        s1 += __shfl_xor_sync(0xffffffffu, s1, 1);
        s1 += __shfl_xor_sync(0xffffffffu, s1, 2);
        lrow[0] = lrow[0] * a0 + s0;
        lrow[1] = lrow[1] * a1 + s1;
        #pragma unroll
        for (int nt = 0; nt < 8; nt++) {
            o[nt][0] *= a0; o[nt][1] *= a0; o[nt][2] *= a1; o[nt][3] *= a1;
        }

        #pragma unroll
        for (int kt = 0; kt < 4; kt++) {
            unsigned ah0, al0, ah1, al1, ah2, al2, ah3, al3;
            split2(c[2 * kt][0],     c[2 * kt][1],     ah0, al0);
            split2(c[2 * kt][2],     c[2 * kt][3],     ah1, al1);
            split2(c[2 * kt + 1][0], c[2 * kt + 1][1], ah2, al2);
            split2(c[2 * kt + 1][2], c[2 * kt + 1][3], ah3, al3);
            const unsigned ko = kt * 32;
            #pragma unroll
            for (int ntp = 0; ntp < 4; ntp++) {
                unsigned bh0, bh1, bh2, bh3, bl0, bl1, bl2, bl3;
                LDSM4(bh0, bh1, bh2, bh3, KVb + 4608 * 4 + boffB + ntp * 16 * AS * 4 + ko);
                LDSM4(bl0, bl1, bl2, bl3, KVb + 6912 * 4 + boffB + ntp * 16 * AS * 4 + ko);
                MMA16816(o[2 * ntp],     ah0, ah1, ah2, ah3, bh0, bh1);
                MMA16816(o[2 * ntp],     ah0, ah1, ah2, ah3, bl0, bl1);
                MMA16816(o[2 * ntp],     al0, al1, al2, al3, bh0, bh1);
                MMA16816(o[2 * ntp + 1], ah0, ah1, ah2, ah3, bh2, bh3);
                MMA16816(o[2 * ntp + 1], ah0, ah1, ah2, ah3, bl2, bl3);
                MMA16816(o[2 * ntp + 1], al0, al1, al2, al3, bh2, bh3);
            }
        }
    }

    if (nch == 1) {
        float inv0 = 1.0f / lrow[0], inv1 = 1.0f / lrow[1];
        const int tok = b * SEQ + i0 + 16 * warp + g;
        #pragma unroll
        for (int nt = 0; nt < 8; nt++) {
            unsigned h, l;
            split2(o[nt][0] * inv0, o[nt][1] * inv0, h, l);
            g_attn_hi[(size_t)tok * 32 + 4 * nt + tg] = h;
            g_attn_lo[(size_t)tok * 32 + 4 * nt + tg] = l;
            split2(o[nt][2] * inv1, o[nt][3] * inv1, h, l);
            g_attn_hi[(size_t)(tok + 8) * 32 + 4 * nt + tg] = h;
            g_attn_lo[(size_t)(tok + 8) * 32 + 4 * nt + tg] = l;
        }
    } else {
        const int pb = b * NCHUNK + cx;
        const int r0 = 16 * warp + g;
        #pragma unroll
        for (int nt = 0; nt < 8; nt++) {
            int col = 8 * nt + 2 * tg;
            *(float2*)&g_part_o[((size_t)pb * 128 + r0) * 64 + col]     = make_float2(o[nt][0], o[nt][1]);
            *(float2*)&g_part_o[((size_t)pb * 128 + r0 + 8) * 64 + col] = make_float2(o[nt][2], o[nt][3]);
        }
        if (tg == 0) {
            g_part_m[pb * 128 + r0] = mrow[0];     g_part_l[pb * 128 + r0] = lrow[0];
            g_part_m[pb * 128 + r0 + 8] = mrow[1]; g_part_l[pb * 128 + r0 + 8] = lrow[1];
        }
    }
}

// ---------------------------------------------------------------------------
// K2b: merge split-j partials (row blocks ib >= 4; up to 8 chunks each)
// ---------------------------------------------------------------------------
__global__ __launch_bounds__(256) void merge_kernel() {
    const int ib = 4 + blockIdx.x;   // 4..31
    const int b = blockIdx.y;
    const int gr = ib >> 2;
    const int nch = gr + 1;
    const int cx0 = 2 * gr * (gr + 1) + (ib - 4 * gr) * (gr + 1);

    const int t = threadIdx.x;
    const int r = t >> 1, half = t & 1;   // r in 0..127

    float mc[8], lc[8], wv[8];
    float mstar = -1e30f;
    for (int c = 0; c < nch; c++) {
        mc[c] = g_part_m[(b * NCHUNK + cx0 + c) * 128 + r];
        lc[c] = g_part_l[(b * NCHUNK + cx0 + c) * 128 + r];
        mstar = fmaxf(mstar, mc[c]);
    }
    float lsum = 0.f;
    for (int c = 0; c < nch; c++) { wv[c] = exp2f(mc[c] - mstar); lsum += wv[c] * lc[c]; }
    const float inv = 1.0f / lsum;

    const int tok = b * SEQ + ib * 128 + r;
    #pragma unroll 4
    for (int j = 0; j < 16; j++) {
        int col = half * 32 + 2 * j;
        float a0 = 0.f, a1 = 0.f;
        for (int c = 0; c < nch; c++) {
            float2 v = *(const float2*)&g_part_o[((size_t)(b * NCHUNK + cx0 + c) * 128 + r) * 64 + col];
            a0 += wv[c] * v.x; a1 += wv[c] * v.y;
        }
        unsigned h, l; split2(a0 * inv, a1 * inv, h, l);
        g_attn_hi[(size_t)tok * 32 + half * 16 + j] = h;
        g_attn_lo[(size_t)tok * 32 + half * 16 + j] = l;
    }
}

// ---------------------------------------------------------------------------
// K3: out = attn @ W_out + b_out. 256 thr, tile 128x128, ldmatrix loads.
// ---------------------------------------------------------------------------
__global__ __launch_bounds__(256) void out_mma_kernel(
    const float* __restrict__ bias, float* __restrict__ out)
{
    extern __shared__ __align__(16) unsigned so[];
    unsigned* Ah = so;
    unsigned* Al = so + 4608;
    unsigned* Bh = so + 9216;
    unsigned* Bl = so + 13824;

    const unsigned sbase = (unsigned)__cvta_generic_to_shared(so);
    const int t = threadIdx.x, lane = t & 31, warp = t >> 5;
    const int g = lane >> 2, tg = lane & 3;
    const int rr = lane & 7, tl = lane >> 3;
    const int m0 = blockIdx.x * 128;
    const int n0 = blockIdx.y * 128;
    const int rb = (warp & 3) * 32;
    const int cbn = (warp >> 2) * 64;

    const unsigned aoff = ((rb + rr + (tl & 1) * 8) * AS + (tl >> 1) * 4) * 4;
    const unsigned boff = ((cbn + rr + ((tl >> 1) & 1) * 8) * AS + (tl & 1) * 4) * 4;

    for (int i = t; i < 1024; i += 256) {
        int r = i >> 3, j = (i & 7) * 4;
        *(float4*)(Ah + r * AS + j) = *(const float4*)(g_attn_hi + (size_t)(m0 + r) * 32 + j);
        *(float4*)(Al + r * AS + j) = *(const float4*)(g_attn_lo + (size_t)(m0 + r) * 32 + j);
        *(float4*)(Bh + r * AS + j) = *(const float4*)(g_woT_hi + (size_t)(n0 + r) * 32 + j);
        *(float4*)(Bl + r * AS + j) = *(const float4*)(g_woT_lo + (size_t)(n0 + r) * 32 + j);
    }
    __syncthreads();

    float c[2][8][4] = {};
    #pragma unroll
    for (int kt = 0; kt < 4; kt++) {
        const unsigned ko = kt * 32;
        unsigned ah[2][4], al[2][4];
        LDSM4(ah[0][0], ah[0][1], ah[0][2], ah[0][3], sbase + aoff + ko);
        LDSM4(ah[1][0], ah[1][1], ah[1][2], ah[1][3], sbase + aoff + 16 * AS * 4 + ko);
        LDSM4(al[0][0], al[0][1], al[0][2], al[0][3], sbase + 4608 * 4 + aoff + ko);
        LDSM4(al[1][0], al[1][1], al[1][2], al[1][3], sbase + 4608 * 4 + aoff + 16 * AS * 4 + ko);
        #pragma unroll
        for (int ntp = 0; ntp < 4; ntp++) {
            unsigned bh0, bh1, bh2, bh3, bl0, bl1, bl2, bl3;
            LDSM4(bh0, bh1, bh2, bh3, sbase + 9216 * 4 + boff + ntp * 16 * AS * 4 + ko);
            LDSM4(bl0, bl1, bl2, bl3, sbase + 13824 * 4 + boff + ntp * 16 * AS * 4 + ko);
            #pragma unroll
            for (int gm = 0; gm < 2; gm++) {
                MMA16816(c[gm][2 * ntp],     ah[gm][0], ah[gm][1], ah[gm][2], ah[gm][3], bh0, bh1);
                MMA16816(c[gm][2 * ntp],     ah[gm][0], ah[gm][1], ah[gm][2], ah[gm][3], bl0, bl1);
                MMA16816(c[gm][2 * ntp],     al[gm][0], al[gm][1], al[gm][2], al[gm][3], bh0, bh1);
                MMA16816(c[gm][2 * ntp + 1], ah[gm][0], ah[gm][1], ah[gm][2], ah[gm][3], bh2, bh3);
                MMA16816(c[gm][2 * ntp + 1], ah[gm][0], ah[gm][1], ah[gm][2], ah[gm][3], bl2, bl3);
                MMA16816(c[gm][2 * ntp + 1], al[gm][0], al[gm][1], al[gm][2], al[gm][3], bh2, bh3);
            }
        }
    }

    #pragma unroll
    for (int gm = 0; gm < 2; gm++) {
        int row = m0 + rb + 16 * gm + g;
        #pragma unroll
        for (int nt = 0; nt < 8; nt++) {
            int col = n0 + cbn + 8 * nt + 2 * tg;
            float b0 = bias[col], b1 = bias[col + 1];
            *(float2*)(out + (size_t)row * DOUT + col)       = make_float2(c[gm][nt][0] + b0, c[gm][nt][1] + b1);
            *(float2*)(out + (size_t)(row + 8) * DOUT + col) = make_float2(c[gm][nt][2] + b0, c[gm][nt][3] + b1);
        }
    }
}

// ---------------------------------------------------------------------------
extern "C" void kernel_launch(void* const* d_in, const int* in_sizes, int n_in,
                              void* d_out, int out_size)
{
    const float* x    = (const float*)d_in[0];
    const float* Wqkv = (const float*)d_in[1];
    const float* Wout = (const float*)d_in[2];
    const float* bout = (const float*)d_in[3];
    float* out = (float*)d_out;

    prep_x_kernel<<<2048, 256>>>(x);
    prep_wqkv_kernel<<<192, 256>>>(Wqkv);
    prep_wout_kernel<<<64, 256>>>(Wout);

    cudaFuncSetAttribute(qkv_mma_kernel, cudaFuncAttributeMaxDynamicSharedMemorySize, 61440);
    qkv_mma_kernel<<<dim3(TOK / 128, 3), 256, 61440>>>();

    cudaFuncSetAttribute(attn_mma_kernel, cudaFuncAttributeMaxDynamicSharedMemorySize, 110592);
    attn_mma_kernel<<<dim3(NCHUNK, NB), 256, 110592>>>();

    merge_kernel<<<dim3(28, NB), 256>>>();

    cudaFuncSetAttribute(out_mma_kernel, cudaFuncAttributeMaxDynamicSharedMemorySize, 73728);
    out_mma_kernel<<<dim3(TOK / 128, DOUT / 128), 256, 73728>>>(bout, out);
}